// round 12
// baseline (speedup 1.0000x reference)
#include <cuda_runtime.h>
#include <cuda_fp16.h>
#include <math.h>
#include <stdint.h>

// ---------------- problem constants ----------------
#define BB 2
#define NN 32768
#define CC 512
#define HH 8
#define DH 64
#define GG 64
#define CD 256
#define ROWS (BB*NN)          // 65536
#define INNER (HH*DH)         // 512
#define EPS 1e-5f
#define TOK_CHUNKS 16         // 2048 tokens per chunk (MMA tokpart)

// ---------------- scratch ----------------
__device__ __half g_xh   [ROWS * CC];
__device__ __half g_wh   [ROWS * INNER];
__device__ __half g_fxh  [ROWS * INNER];
__device__ float  g_npart[512 * 512];
__device__ float  g_norm [BB * HH * GG];
__device__ float  g_tpart[16 * TOK_CHUNKS * 4096];
__device__ float  g_tok  [16 * 4096];
__device__ float  g_ot   [16 * 4096];
__device__ float  g_ckv  [2 * 16 * 4096];   // [mat][bh][row][64]
__device__ __half g_MTh  [BB * 512 * 512];
__device__ __half g_WcatTh[1024 * 512];
__device__ float  g_bcomb[512];

// ---------------- helpers ----------------
__device__ __forceinline__ void cp16(void* dst, const void* src) {
    unsigned d = (unsigned)__cvta_generic_to_shared(dst);
    asm volatile("cp.async.cg.shared.global [%0], [%1], 16;" :: "r"(d), "l"(src));
}
__device__ __forceinline__ void mma_f16(float* c, const unsigned* a, const unsigned* b) {
    asm volatile(
        "mma.sync.aligned.m16n8k16.row.col.f32.f16.f16.f32 "
        "{%0,%1,%2,%3},{%4,%5,%6,%7},{%8,%9},{%0,%1,%2,%3};"
        : "+f"(c[0]), "+f"(c[1]), "+f"(c[2]), "+f"(c[3])
        : "r"(a[0]), "r"(a[1]), "r"(a[2]), "r"(a[3]), "r"(b[0]), "r"(b[1]));
}
#define LDSM4(r0, r1, r2, r3, addr) \
    asm volatile("ldmatrix.sync.aligned.m8n8.x4.shared.b16 {%0,%1,%2,%3}, [%4];" \
        : "=r"(r0), "=r"(r1), "=r"(r2), "=r"(r3) : "r"(addr))
#define LDSM4T(r0, r1, r2, r3, addr) \
    asm volatile("ldmatrix.sync.aligned.m8n8.x4.trans.shared.b16 {%0,%1,%2,%3}, [%4];" \
        : "=r"(r0), "=r"(r1), "=r"(r2), "=r"(r3) : "r"(addr))

// ============================================================
// fused prologue: role by block range
//   blocks [0, 2048): x fp32 -> xh fp16 (grid-stride)
//   blocks [2048, 3072): Wfx -> WcatT rows 512..1023 (transposed fp16)
//   blocks [3072, 3584): Wcomb -> WcatT rows 0..511 + bcomb (block 3072)
// ============================================================
#define ROUND_BLKS 2048
#define WFX_BLKS 1024
#define WCOMB_BLKS 512
#define PREP_BLKS (ROUND_BLKS + WFX_BLKS + WCOMB_BLKS)

__global__ __launch_bounds__(256) void prep_kernel(
    const float* __restrict__ x, __half* __restrict__ xh,
    const float* __restrict__ Wfx,
    const float* __restrict__ Wx, const float* __restrict__ Wslice,
    const float* __restrict__ temp,
    const float* __restrict__ bx, const float* __restrict__ bslice,
    __half* __restrict__ WcatT, float* __restrict__ bcomb)
{
    const int tid = threadIdx.x;
    const int blk = blockIdx.x;

    if (blk < ROUND_BLKS) {
        const int n4 = ROWS * CC / 4;
        int idx = blk * 256 + tid;
        const int stride = ROUND_BLKS * 256;
        for (; idx < n4; idx += stride) {
            float4 v = ((const float4*)x)[idx];
            __half2* o = (__half2*)xh + idx * 2;
            o[0] = __floats2half2_rn(v.x, v.y);
            o[1] = __floats2half2_rn(v.z, v.w);
        }
    } else if (blk < ROUND_BLKS + WFX_BLKS) {
        int idx = (blk - ROUND_BLKS) * 256 + tid;   // 0..262143
        int k = idx >> 9;
        int n = idx & 511;
        WcatT[(size_t)(512 + n) * 512 + k] = __float2half_rn(Wfx[(size_t)k * 512 + n]);
    } else {
        __shared__ float sWs[4096];
        __shared__ float sx[512];
        __shared__ float sit[8];
        const int cr = blk - (ROUND_BLKS + WFX_BLKS);   // k index 0..511
        for (int i = tid; i < 4096; i += 256) sWs[i] = Wslice[i];
        sx[tid] = Wx[(size_t)cr * 512 + tid];
        sx[tid + 256] = Wx[(size_t)cr * 512 + tid + 256];
        if (tid < 8) {
            float tv = temp[tid];
            sit[tid] = 1.0f / fminf(fmaxf(tv, 0.1f), 5.0f);
        }
        __syncthreads();
#pragma unroll
        for (int rep = 0; rep < 2; rep++) {
            const int o = tid + rep * 256;
            const int h = o >> 6, gg = o & 63;
            float acc = 0.f;
#pragma unroll 8
            for (int d = 0; d < 64; d++)
                acc += sx[h*64 + d] * sWs[d*64 + gg];
            WcatT[(size_t)o * 512 + cr] = __float2half_rn(acc * sit[h]);
            if (cr == 0) {
                float acc2 = bslice[gg];
                for (int d = 0; d < 64; d++)
                    acc2 += bx[h*64 + d] * sWs[d*64 + gg];
                bcomb[o] = acc2 * sit[h];
            }
        }
    }
}

// ============================================================
// ck/cv projections: ckv[mat][bh][row][64] = ctx[bh] @ Wc{k,v} + b
// grid (2, 16), 256 threads: row = tid>>2, 16 cols per thread.
// ============================================================
__global__ __launch_bounds__(256) void ckcv_kernel(
    const float* __restrict__ ctx,
    const float* __restrict__ Wck, const float* __restrict__ bck,
    const float* __restrict__ Wcv, const float* __restrict__ bcv,
    float* __restrict__ ckv)
{
    const int mat = blockIdx.x;
    const int bh  = blockIdx.y;
    const int tid = threadIdx.x;
    const int i   = tid >> 2;
    const int c0  = (tid & 3) * 16;
    const float* W  = mat ? Wcv : Wck;
    const float* bb = mat ? bcv : bck;
    const float* crow = ctx + ((size_t)bh * 64 + i) * 256;

    float acc[16];
#pragma unroll
    for (int j = 0; j < 16; j++) acc[j] = bb[c0 + j];
    for (int d = 0; d < 256; d++) {
        float xv = crow[d];
        const float4* W4 = (const float4*)(W + (size_t)d * 64 + c0);
#pragma unroll
        for (int j4 = 0; j4 < 4; j4++) {
            float4 wv = W4[j4];
            acc[j4*4+0] += xv*wv.x; acc[j4*4+1] += xv*wv.y;
            acc[j4*4+2] += xv*wv.z; acc[j4*4+3] += xv*wv.w;
        }
    }
    float* o = ckv + ((size_t)(mat * 16 + bh) * 64 + i) * 64 + c0;
#pragma unroll
    for (int j = 0; j < 16; j++) o[j] = acc[j];
}

// ============================================================
// FP16 GEMM 128x128x32, 8 warps (warp tile 32x64), 4-stage cp.async,
// ldmatrix fragment loads, register-resident softmax epilogue.
// ============================================================
#define AH 40
#define STG_BYTES 10240
#define SM_GEMM (8 * STG_BYTES)

template<int MODE>
__global__ __launch_bounds__(256, 2) void f16_gemm(
    const __half* __restrict__ A, const __half* __restrict__ BT,
    const float* __restrict__ biasA, const float* __restrict__ biasB,
    __half* __restrict__ wOut, __half* __restrict__ fxOut,
    float* __restrict__ outF, float* __restrict__ npart,
    int K, int bRowsPerBatch, int bMatStride)
{
    extern __shared__ char smem[];

    const int tid  = threadIdx.x;
    const int lane = tid & 31;
    const int warp = tid >> 5;
    const int wr   = warp >> 1;
    const int wc   = warp & 1;
    const int row0 = blockIdx.y * 128;
    const int col0 = blockIdx.x * 128;

    const __half* Bp = BT;
    if (bRowsPerBatch) Bp += (size_t)(row0 / bRowsPerBatch) * (size_t)bMatStride;

    float c[2][8][4];
#pragma unroll
    for (int i = 0; i < 2; i++)
#pragma unroll
        for (int j = 0; j < 8; j++)
#pragma unroll
            for (int r = 0; r < 4; r++) c[i][j][r] = 0.f;

    const int g = lane >> 2;
    const int t = lane & 3;

    const uint32_t As0 = (uint32_t)__cvta_generic_to_shared(smem);
    const uint32_t Bs0 = As0 + 4 * STG_BYTES;
    uint32_t aOff[2], bOff[4];
#pragma unroll
    for (int i = 0; i < 2; i++)
        aOff[i] = (uint32_t)(((wr*32 + i*16 + (lane & 15)) * AH + ((lane >> 4) << 3)) * 2);
#pragma unroll
    for (int jp = 0; jp < 4; jp++)
        bOff[jp] = (uint32_t)(((wc*64 + jp*16 + ((lane >> 4) << 3) + (lane & 7)) * AH
                               + (((lane >> 3) & 1) << 3)) * 2);

    const int sr  = tid >> 2;
    const int skc = (tid & 3) * 8;

    auto stage = [&](int kt, int buf) {
        __half* a = (__half*)(smem + buf * STG_BYTES);
        __half* b = (__half*)(smem + 4 * STG_BYTES + buf * STG_BYTES);
        const int k0 = kt << 5;
#pragma unroll
        for (int it = 0; it < 2; it++) {
            int r = sr + it * 64;
            cp16(&a[r * AH + skc], A  + (size_t)(row0 + r) * K + k0 + skc);
            cp16(&b[r * AH + skc], Bp + (size_t)(col0 + r) * K + k0 + skc);
        }
    };

    const int ntiles = K >> 5;
    stage(0, 0); asm volatile("cp.async.commit_group;");
    stage(1, 1); asm volatile("cp.async.commit_group;");
    stage(2, 2); asm volatile("cp.async.commit_group;");

    for (int kt = 0; kt < ntiles; kt++) {
        asm volatile("cp.async.wait_group 2;");
        __syncthreads();
        if (kt + 3 < ntiles) stage(kt + 3, (kt + 3) & 3);
        asm volatile("cp.async.commit_group;");

        const uint32_t aBuf = As0 + (kt & 3) * STG_BYTES;
        const uint32_t bBuf = Bs0 + (kt & 3) * STG_BYTES;
#pragma unroll
        for (int ks = 0; ks < 2; ks++) {
            const uint32_t kbB = ks * 32;
            unsigned a[2][4], b[8][2];
#pragma unroll
            for (int i = 0; i < 2; i++)
                LDSM4(a[i][0], a[i][1], a[i][2], a[i][3], aBuf + aOff[i] + kbB);
#pragma unroll
            for (int jp = 0; jp < 4; jp++)
                LDSM4(b[jp*2][0], b[jp*2][1], b[jp*2+1][0], b[jp*2+1][1],
                      bBuf + bOff[jp] + kbB);
#pragma unroll
            for (int i = 0; i < 2; i++)
#pragma unroll
                for (int j = 0; j < 8; j++)
                    mma_f16(c[i][j], a[i], b[j]);
        }
        __syncthreads();
    }

    if (MODE == 1 && col0 < 512) {
        const int colbase = col0 + wc * 64;
        float bv[16];
#pragma unroll
        for (int j = 0; j < 8; j++) {
            bv[j*2]   = biasA[colbase + j*8 + t*2];
            bv[j*2+1] = biasA[colbase + j*8 + t*2 + 1];
        }
#pragma unroll
        for (int i = 0; i < 2; i++)
#pragma unroll
            for (int j = 0; j < 8; j++) {
                c[i][j][0] += bv[j*2];   c[i][j][1] += bv[j*2+1];
                c[i][j][2] += bv[j*2];   c[i][j][3] += bv[j*2+1];
            }

        float cs[16];
#pragma unroll
        for (int m = 0; m < 16; m++) cs[m] = 0.f;

#pragma unroll
        for (int i = 0; i < 2; i++)
#pragma unroll
            for (int h2 = 0; h2 < 2; h2++) {
                float mx = -1e30f;
#pragma unroll
                for (int j = 0; j < 8; j++)
                    mx = fmaxf(mx, fmaxf(c[i][j][h2*2], c[i][j][h2*2+1]));
                mx = fmaxf(mx, __shfl_xor_sync(0xffffffffu, mx, 1));
                mx = fmaxf(mx, __shfl_xor_sync(0xffffffffu, mx, 2));
                float s = 0.f;
#pragma unroll
                for (int j = 0; j < 8; j++) {
                    float e0 = __expf(c[i][j][h2*2]   - mx);
                    float e1 = __expf(c[i][j][h2*2+1] - mx);
                    c[i][j][h2*2] = e0; c[i][j][h2*2+1] = e1;
                    s += e0 + e1;
                }
                s += __shfl_xor_sync(0xffffffffu, s, 1);
                s += __shfl_xor_sync(0xffffffffu, s, 2);
                const float is = 1.0f / s;
                const size_t row = (size_t)(row0 + wr*32 + i*16 + h2*8 + g);
#pragma unroll
                for (int j = 0; j < 8; j++) {
                    __half2 h = __floats2half2_rn(c[i][j][h2*2]*is, c[i][j][h2*2+1]*is);
                    *(__half2*)(wOut + row * 512 + colbase + j*8 + t*2) = h;
                    float2 f = __half22float2(h);
                    cs[j*2] += f.x; cs[j*2+1] += f.y;
                }
            }

#pragma unroll
        for (int m = 0; m < 16; m++) {
            cs[m] += __shfl_xor_sync(0xffffffffu, cs[m], 4);
            cs[m] += __shfl_xor_sync(0xffffffffu, cs[m], 8);
            cs[m] += __shfl_xor_sync(0xffffffffu, cs[m], 16);
        }
        float* npsum = (float*)smem;
        if (lane < 4) {
#pragma unroll
            for (int j = 0; j < 8; j++) {
                npsum[wr*128 + wc*64 + j*8 + lane*2]     = cs[j*2];
                npsum[wr*128 + wc*64 + j*8 + lane*2 + 1] = cs[j*2+1];
            }
        }
        __syncthreads();
        if (tid < 128)
            npart[(size_t)blockIdx.y * 512 + col0 + tid] =
                npsum[tid] + npsum[128+tid] + npsum[256+tid] + npsum[384+tid];
    } else if (MODE == 1) {
        const int cg = col0 - 512 + wc * 64;
#pragma unroll
        for (int i = 0; i < 2; i++) {
            int rm = row0 + wr*32 + i*16 + g;
#pragma unroll
            for (int j = 0; j < 8; j++) {
                int cn = cg + j*8 + t*2;
                float b0 = biasB[cn], b1 = biasB[cn + 1];
                *(__half2*)(fxOut + (size_t)rm * 512 + cn) =
                    __floats2half2_rn(c[i][j][0] + b0, c[i][j][1] + b1);
                *(__half2*)(fxOut + (size_t)(rm + 8) * 512 + cn) =
                    __floats2half2_rn(c[i][j][2] + b0, c[i][j][3] + b1);
            }
        }
    } else {
        const int cg = col0 + wc * 64;
#pragma unroll
        for (int i = 0; i < 2; i++) {
            int rm = row0 + wr*32 + i*16 + g;
#pragma unroll
            for (int j = 0; j < 8; j++) {
                int cn = cg + j*8 + t*2;
                float b0 = biasA[cn], b1 = biasA[cn + 1];
                *(float2*)(outF + (size_t)rm * 512 + cn) =
                    make_float2(c[i][j][0] + b0, c[i][j][1] + b1);
                *(float2*)(outF + (size_t)(rm + 8) * 512 + cn) =
                    make_float2(c[i][j][2] + b0, c[i][j][3] + b1);
            }
        }
    }
}

// ============================================================
// norm reduce
// ============================================================
__global__ void norm_reduce_kernel(const float* __restrict__ npart,
                                   float* __restrict__ norm)
{
    int e = blockIdx.x * 256 + threadIdx.x;
    int b = e >> 9, hg = e & 511;
    float s = 0.f;
    for (int rb = 0; rb < 256; rb++)
        s += npart[((size_t)(b * 256 + rb)) * 512 + hg];
    norm[e] = s;
}

// ============================================================
// tokens partials via tensor cores (64-token tiles, 2 CTA/SM)
// ============================================================
#define WT 72
#define TPT_TILE_H (64 * WT)          // 4608 halves
#define TPT_SMEM (4 * TPT_TILE_H * 2) // 36864 B

__global__ __launch_bounds__(256, 2) void tokpart_mma_kernel(
    const __half* __restrict__ fx, const __half* __restrict__ w,
    float* __restrict__ part)
{
    extern __shared__ char smem[];
    const int chunk = blockIdx.x;
    const int bh = blockIdx.y;
    const int b = bh >> 3, h = bh & 7;
    const size_t rbase = (size_t)b * NN + (size_t)chunk * 2048;

    const int tid  = threadIdx.x;
    const int lane = tid & 31;
    const int warp = tid >> 5;
    const int wm   = warp >> 1;
    const int wn   = warp & 1;

    const uint32_t S0 = (uint32_t)__cvta_generic_to_shared(smem);

    float c[4][4];
#pragma unroll
    for (int nj = 0; nj < 4; nj++)
#pragma unroll
        for (int r = 0; r < 4; r++) c[nj][r] = 0.f;

    const uint32_t aOff = (uint32_t)(((((lane >> 4) << 3) + (lane & 7)) * WT
                           + wm*16 + (((lane >> 3) & 1) << 3)) * 2);
    uint32_t bOff[2];
#pragma unroll
    for (int p2 = 0; p2 < 2; p2++)
        bOff[p2] = (uint32_t)((((((lane >> 3) & 1) << 3) + (lane & 7)) * WT
                    + wn*32 + p2*16 + ((lane >> 4) << 3)) * 2);

    auto stage = [&](int kt, int buf) {
        __half* wsb = (__half*)smem + buf * TPT_TILE_H;
        __half* fsb = (__half*)smem + 2 * TPT_TILE_H + buf * TPT_TILE_H;
#pragma unroll
        for (int it = 0; it < 2; it++) {
            int s = tid + it * 256;          // 0..511
            int r = s >> 3;                  // 0..63
            int c8 = (s & 7) * 8;
            size_t row = rbase + (size_t)kt * 64 + r;
            cp16(&wsb[r * WT + c8], w  + row * 512 + h * 64 + c8);
            cp16(&fsb[r * WT + c8], fx + row * 512 + h * 64 + c8);
        }
    };

    stage(0, 0);
    asm volatile("cp.async.commit_group;");

    for (int kt = 0; kt < 32; kt++) {
        asm volatile("cp.async.wait_group 0;");
        __syncthreads();
        if (kt + 1 < 32) {
            stage(kt + 1, (kt + 1) & 1);
            asm volatile("cp.async.commit_group;");
        }
        const int buf = kt & 1;
        const uint32_t wBuf = S0 + buf * TPT_TILE_H * 2;
        const uint32_t fBuf = S0 + (2 + buf) * TPT_TILE_H * 2;
#pragma unroll
        for (int ks = 0; ks < 4; ks++) {
            const uint32_t ksB = (uint32_t)(ks * 16 * WT * 2);
            unsigned a[4], bb[4][2];
            LDSM4T(a[0], a[1], a[2], a[3], wBuf + aOff + ksB);
            LDSM4T(bb[0][0], bb[0][1], bb[1][0], bb[1][1], fBuf + bOff[0] + ksB);
            LDSM4T(bb[2][0], bb[2][1], bb[3][0], bb[3][1], fBuf + bOff[1] + ksB);
#pragma unroll
            for (int nj = 0; nj < 4; nj++)
                mma_f16(c[nj], a, bb[nj]);
        }
        __syncthreads();
    }

    const int g4 = lane >> 2;
    const int t  = lane & 3;
    float* p = part + ((size_t)bh * TOK_CHUNKS + chunk) * 4096;
#pragma unroll
    for (int nj = 0; nj < 4; nj++) {
        int col = wn*32 + nj*8 + t*2;
        *(float2*)&p[(wm*16 + g4) * 64 + col]     = make_float2(c[nj][0], c[nj][1]);
        *(float2*)&p[(wm*16 + g4 + 8) * 64 + col] = make_float2(c[nj][2], c[nj][3]);
    }
}

__global__ void tok_reduce_kernel(const float* __restrict__ part,
                                  float* __restrict__ tok)
{
    int idx = blockIdx.x * 256 + threadIdx.x;
    int bh = idx >> 12, gd = idx & 4095;
    float s = 0.f;
    for (int c = 0; c < TOK_CHUNKS; c++)
        s += part[((size_t)bh * TOK_CHUNKS + c) * 4096 + gd];
    tok[idx] = s;
}

// ============================================================
// tiny attention (ck/cv precomputed in ckv)
// ============================================================
template<int NC>
__device__ __forceinline__ void row_gemm_cols(
    const float* __restrict__ xrow, int Kd,
    const float* __restrict__ W, const float* __restrict__ bias,
    float* __restrict__ outp, int c0)
{
    float acc[NC];
#pragma unroll
    for (int j = 0; j < NC; j++) acc[j] = bias[c0 + j];
    for (int d = 0; d < Kd; d++) {
        float xv = xrow[d];
        const float4* W4 = (const float4*)(W + (size_t)d * 64 + c0);
#pragma unroll
        for (int j4 = 0; j4 < NC/4; j4++) {
            float4 wv = W4[j4];
            acc[j4*4+0] += xv*wv.x; acc[j4*4+1] += xv*wv.y;
            acc[j4*4+2] += xv*wv.z; acc[j4*4+3] += xv*wv.w;
        }
    }
#pragma unroll
    for (int j = 0; j < NC; j++) outp[c0 + j] = acc[j];
}

__device__ __forceinline__ void attn_row(
    const float* __restrict__ qrow, const float* __restrict__ Kt,
    const float* __restrict__ Vt, float* __restrict__ o)
{
    float qr[64];
#pragma unroll
    for (int d = 0; d < 64; d++) qr[d] = qrow[d];
    float sc[64];
    float m = -1e30f;
    for (int j = 0; j < 64; j++) {
        const float4* kr = (const float4*)(Kt + j * 64);
        float a = 0.f;
#pragma unroll
        for (int d4 = 0; d4 < 16; d4++) {
            float4 kv = kr[d4];
            a += qr[d4*4]*kv.x + qr[d4*4+1]*kv.y + qr[d4*4+2]*kv.z + qr[d4*4+3]*kv.w;
        }
        sc[j] = a * 0.125f;
        m = fmaxf(m, sc[j]);
    }
    float s = 0.f;
#pragma unroll
    for (int j = 0; j < 64; j++) { sc[j] = expf(sc[j] - m); s += sc[j]; }
    float is = 1.0f / s;
#pragma unroll
    for (int d = 0; d < 64; d++) o[d] = 0.f;
    for (int j = 0; j < 64; j++) {
        float p = sc[j] * is;
        const float4* vr = (const float4*)(Vt + j * 64);
#pragma unroll
        for (int d4 = 0; d4 < 16; d4++) {
            float4 vv = vr[d4];
            o[d4*4+0] += p*vv.x; o[d4*4+1] += p*vv.y;
            o[d4*4+2] += p*vv.z; o[d4*4+3] += p*vv.w;
        }
    }
}

__global__ __launch_bounds__(256) void attn_kernel(
    const float* __restrict__ ckv,
    const float* __restrict__ Wq, const float* __restrict__ bq,
    const float* __restrict__ Wk, const float* __restrict__ bk,
    const float* __restrict__ Wv, const float* __restrict__ bv,
    const float* __restrict__ Wcq, const float* __restrict__ bcq,
    const float* __restrict__ smix,
    const float* __restrict__ tokens, const float* __restrict__ norm,
    float* __restrict__ ot)
{
    extern __shared__ float sm[];
    float* s_tok = sm;
    float* s_q   = sm + 4096;
    float* s_k   = sm + 2*4096;
    float* s_v   = sm + 3*4096;
    float* s_cq  = sm + 4*4096;
    float* s_ck  = sm + 5*4096;
    float* s_cv  = sm + 6*4096;

    const int bh = blockIdx.x;
    const int tid = threadIdx.x;

    for (int idx = tid; idx < 4096; idx += 256) {
        int row = idx >> 6;
        float inv = 1.0f / (norm[bh*64 + row] + EPS);
        s_tok[idx] = tokens[(size_t)bh*4096 + idx] * inv;
        s_ck[idx] = ckv[(size_t)bh * 4096 + idx];
        s_cv[idx] = ckv[(size_t)(16 + bh) * 4096 + idx];
    }
    __syncthreads();

    {
        const int pid = tid >> 6;
        const int i   = tid & 63;
        const float* W; const float* bb; float* dst;
        if (pid == 0)      { W = Wq;  bb = bq;  dst = s_q;  }
        else if (pid == 1) { W = Wk;  bb = bk;  dst = s_k;  }
        else if (pid == 2) { W = Wv;  bb = bv;  dst = s_v;  }
        else               { W = Wcq; bb = bcq; dst = s_cq; }
        row_gemm_cols<64>(&s_tok[i*64], 64, W, bb, &dst[i*64], 0);
    }
    __syncthreads();

    if (tid < 64) {
        float o[64];
        attn_row(&s_q[tid*64], s_k, s_v, o);
#pragma unroll
        for (int d = 0; d < 64; d++) s_tok[tid*64 + d] = o[d];
    } else if (tid < 128) {
        const int i = tid - 64;
        float o[64];
        attn_row(&s_cq[i*64], s_ck, s_cv, o);
#pragma unroll
        for (int d = 0; d < 64; d++) s_cq[i*64 + d] = o[d];
    }
    __syncthreads();

    const float gmix = 1.0f / (1.0f + expf(-smix[0]));
    for (int idx = tid; idx < 4096; idx += 256)
        ot[(size_t)bh*4096 + idx] = gmix * s_tok[idx] + (1.0f - gmix) * s_cq[idx];
}

// ============================================================
// M^T[b][c][hg] = sum_d out_tok[b,hg,d] * Wo[h*64+d, c]  (fp16 out)
// ============================================================
__global__ __launch_bounds__(256) void m_kernel(
    const float* __restrict__ Wo, const float* __restrict__ ot,
    __half* __restrict__ MT)
{
    __shared__ float s_ot[4096];
    __shared__ float s_wo[64 * 128];
    const int bh = blockIdx.y;
    const int h = bh & 7, b = bh >> 3;
    const int c0 = blockIdx.x * 128;
    const int tid = threadIdx.x;

    for (int idx = tid; idx < 1024; idx += 256)
        ((float4*)s_ot)[idx] = ((const float4*)(ot + (size_t)bh * 4096))[idx];
    for (int idx = tid; idx < 2048; idx += 256) {
        int d = idx >> 5;
        int c4 = idx & 31;
        ((float4*)s_wo)[idx] = *(const float4*)(Wo + (size_t)(h*64 + d)*512 + c0 + c4*4);
    }
    __syncthreads();

    const int g0 = (tid >> 3) * 2;
    const int ct = (tid & 7) * 16;
    float acc[2][16];
#pragma unroll
    for (int g = 0; g < 2; g++)
#pragma unroll
        for (int c = 0; c < 16; c++) acc[g][c] = 0.f;

    for (int d = 0; d < 64; d++) {
        float a0 = s_ot[g0*64 + d];
        float a1 = s_ot[(g0+1)*64 + d];
#pragma unroll
        for (int c4 = 0; c4 < 4; c4++) {
            float4 wv = *(const float4*)&s_wo[d*128 + ct + c4*4];
            acc[0][c4*4+0]+=a0*wv.x; acc[0][c4*4+1]+=a0*wv.y; acc[0][c4*4+2]+=a0*wv.z; acc[0][c4*4+3]+=a0*wv.w;
            acc[1][c4*4+0]+=a1*wv.x; acc[1][c4*4+1]+=a1*wv.y; acc[1][c4*4+2]+=a1*wv.z; acc[1][c4*4+3]+=a1*wv.w;
        }
    }

#pragma unroll
    for (int g = 0; g < 2; g++) {
        int hg = h*64 + g0 + g;
#pragma unroll
        for (int c = 0; c < 16; c++)
            MT[(size_t)b * 262144 + (size_t)(c0 + ct + c) * 512 + hg] =
                __float2half_rn(acc[g][c]);
    }
}

// ============================================================
// host launcher
// ============================================================
extern "C" void kernel_launch(void* const* d_in, const int* in_sizes, int n_in,
                              void* d_out, int out_size)
{
    const float* x      = (const float*)d_in[0];
    const float* ctx    = (const float*)d_in[1];
    const float* Wx     = (const float*)d_in[2];
    const float* bx     = (const float*)d_in[3];
    const float* Wfx    = (const float*)d_in[4];
    const float* bfx    = (const float*)d_in[5];
    const float* Wslice = (const float*)d_in[6];
    const float* bslice = (const float*)d_in[7];
    const float* temp   = (const float*)d_in[8];
    const float* Wq     = (const float*)d_in[9];
    const float* bq     = (const float*)d_in[10];
    const float* Wk     = (const float*)d_in[11];
    const float* bk     = (const float*)d_in[12];
    const float* Wv     = (const float*)d_in[13];
    const float* bv     = (const float*)d_in[14];
    const float* Wcq    = (const float*)d_in[15];
    const float* bcq    = (const float*)d_in[16];
    const float* Wck    = (const float*)d_in[17];
    const float* bck    = (const float*)d_in[18];
    const float* Wcv    = (const float*)d_in[19];
    const float* bcv    = (const float*)d_in[20];
    const float* smix   = (const float*)d_in[21];
    const float* Wo     = (const float*)d_in[22];
    const float* bo     = (const float*)d_in[23];
    float* out = (float*)d_out;

    void *p;
    cudaGetSymbolAddress(&p, g_xh);    __half* xh    = (__half*)p;
    cudaGetSymbolAddress(&p, g_wh);    __half* wh    = (__half*)p;
    cudaGetSymbolAddress(&p, g_fxh);   __half* fxh   = (__half*)p;
    cudaGetSymbolAddress(&p, g_npart); float* npart  = (float*)p;
    cudaGetSymbolAddress(&p, g_norm);  float* norm   = (float*)p;
    cudaGetSymbolAddress(&p, g_tpart); float* tpart  = (float*)p;
    cudaGetSymbolAddress(&p, g_tok);   float* tok    = (float*)p;
    cudaGetSymbolAddress(&p, g_ot);    float* ot     = (float*)p;
    cudaGetSymbolAddress(&p, g_ckv);   float* ckv    = (float*)p;
    cudaGetSymbolAddress(&p, g_MTh);   __half* MTh   = (__half*)p;
    cudaGetSymbolAddress(&p, g_WcatTh);__half* WcatT = (__half*)p;
    cudaGetSymbolAddress(&p, g_bcomb); float* bcomb  = (float*)p;

    cudaFuncSetAttribute(f16_gemm<1>, cudaFuncAttributeMaxDynamicSharedMemorySize, SM_GEMM);
    cudaFuncSetAttribute(f16_gemm<0>, cudaFuncAttributeMaxDynamicSharedMemorySize, SM_GEMM);
    cudaFuncSetAttribute(tokpart_mma_kernel, cudaFuncAttributeMaxDynamicSharedMemorySize, TPT_SMEM);
    cudaFuncSetAttribute(attn_kernel, cudaFuncAttributeMaxDynamicSharedMemorySize, 7*4096*4);

    // 0: fused prologue (x->fp16 | WcatT assembly | bcomb)
    prep_kernel<<<PREP_BLKS, 256>>>(x, xh, Wfx, Wx, Wslice, temp, bx, bslice, WcatT, bcomb);
    // 0b: ck/cv projections (independent of GEMM)
    ckcv_kernel<<<dim3(2, 16), 256>>>(ctx, Wck, bck, Wcv, bcv, ckv);
    // 1: merged fp16 GEMM: softmax->wh(+npart) | bias->fxh
    f16_gemm<1><<<dim3(8, 512), 256, SM_GEMM>>>(
        xh, WcatT, bcomb, bfx, wh, fxh, nullptr, npart, CC, 0, 0);
    // 2: norm
    norm_reduce_kernel<<<4, 256>>>(npart, norm);
    // 3: tokens = w^T @ fx (tensor cores)
    tokpart_mma_kernel<<<dim3(TOK_CHUNKS, 16), 256, TPT_SMEM>>>(fxh, wh, tpart);
    tok_reduce_kernel<<<256, 256>>>(tpart, tok);
    // 4: tiny attention
    attn_kernel<<<16, 256, 7*4096*4>>>(ckv, Wq, bq, Wk, bk, Wv, bv,
                                       Wcq, bcq, smix, tok, norm, ot);
    // 5: fold out_tok @ Wo -> M^T (fp16)
    m_kernel<<<dim3(4, 16), 256>>>(Wo, ot, MTh);
    // 6: out = w @ M[b] + bo (fp16 GEMM, B per-batch)
    f16_gemm<0><<<dim3(4, 512), 256, SM_GEMM>>>(
        wh, MTh, bo, nullptr, nullptr, nullptr, out, nullptr, INNER, NN, 512*512);
}

// round 13
// speedup vs baseline: 1.1012x; 1.1012x over previous
#include <cuda_runtime.h>
#include <cuda_fp16.h>
#include <math.h>
#include <stdint.h>

// ---------------- problem constants ----------------
#define BB 2
#define NN 32768
#define CC 512
#define HH 8
#define DH 64
#define GG 64
#define CD 256
#define ROWS (BB*NN)          // 65536
#define INNER (HH*DH)         // 512
#define EPS 1e-5f
#define TOK_CHUNKS 16         // 2048 tokens per chunk (MMA tokpart)

// ---------------- scratch ----------------
__device__ __half g_xh   [ROWS * CC];
__device__ __half g_wh   [ROWS * INNER];
__device__ __half g_fxh  [ROWS * INNER];
__device__ float  g_npart[512 * 512];
__device__ float  g_np2  [32 * 512];
__device__ float  g_norm [BB * HH * GG];
__device__ float  g_tpart[16 * TOK_CHUNKS * 4096];
__device__ float  g_tok  [16 * 4096];
__device__ float  g_ot   [16 * 4096];
__device__ __half g_MTh  [BB * 512 * 512];
__device__ __half g_WcatTh[1024 * 512];
__device__ float  g_bcomb[512];

// ---------------- helpers ----------------
__device__ __forceinline__ void cp16(void* dst, const void* src) {
    unsigned d = (unsigned)__cvta_generic_to_shared(dst);
    asm volatile("cp.async.cg.shared.global [%0], [%1], 16;" :: "r"(d), "l"(src));
}
__device__ __forceinline__ void mma_f16(float* c, const unsigned* a, const unsigned* b) {
    asm volatile(
        "mma.sync.aligned.m16n8k16.row.col.f32.f16.f16.f32 "
        "{%0,%1,%2,%3},{%4,%5,%6,%7},{%8,%9},{%0,%1,%2,%3};"
        : "+f"(c[0]), "+f"(c[1]), "+f"(c[2]), "+f"(c[3])
        : "r"(a[0]), "r"(a[1]), "r"(a[2]), "r"(a[3]), "r"(b[0]), "r"(b[1]));
}
#define LDSM4(r0, r1, r2, r3, addr) \
    asm volatile("ldmatrix.sync.aligned.m8n8.x4.shared.b16 {%0,%1,%2,%3}, [%4];" \
        : "=r"(r0), "=r"(r1), "=r"(r2), "=r"(r3) : "r"(addr))
#define LDSM4T(r0, r1, r2, r3, addr) \
    asm volatile("ldmatrix.sync.aligned.m8n8.x4.trans.shared.b16 {%0,%1,%2,%3}, [%4];" \
        : "=r"(r0), "=r"(r1), "=r"(r2), "=r"(r3) : "r"(addr))

// ============================================================
// x (fp32) -> xh (fp16)
// ============================================================
__global__ void round_f16_kernel(const float* __restrict__ in,
                                 __half* __restrict__ out, int n4)
{
    int idx = blockIdx.x * blockDim.x + threadIdx.x;
    int stride = gridDim.x * blockDim.x;
    for (; idx < n4; idx += stride) {
        float4 v = ((const float4*)in)[idx];
        __half2* o = (__half2*)out + idx * 2;
        o[0] = __floats2half2_rn(v.x, v.y);
        o[1] = __floats2half2_rn(v.z, v.w);
    }
}

// Wfx -> WcatTh rows 512..1023 (transposed [n][k], fp16)
__global__ void wfx_cat_kernel(const float* __restrict__ Wfx,
                               __half* __restrict__ WcatT)
{
    int idx = blockIdx.x * blockDim.x + threadIdx.x;
    int k = idx >> 9;
    int n = idx & 511;
    WcatT[(size_t)(512 + n) * 512 + k] = __float2half_rn(Wfx[(size_t)k * 512 + n]);
}

// Wcomb -> WcatTh rows 0..511 (transposed, fp16), bcomb in block 0
__global__ __launch_bounds__(512) void wcomb_kernel(
    const float* __restrict__ Wx, const float* __restrict__ Wslice,
    const float* __restrict__ temp,
    const float* __restrict__ bx, const float* __restrict__ bslice,
    __half* __restrict__ WcatT, float* __restrict__ bcomb)
{
    __shared__ float sWs[4096];
    __shared__ float sx[512];
    __shared__ float sit[8];
    const int tid = threadIdx.x;
    const int cr = blockIdx.x;
    for (int i = tid; i < 4096; i += 512) sWs[i] = Wslice[i];
    sx[tid] = Wx[(size_t)cr * 512 + tid];
    if (tid < 8) {
        float tv = temp[tid];
        sit[tid] = 1.0f / fminf(fmaxf(tv, 0.1f), 5.0f);
    }
    __syncthreads();
    const int h = tid >> 6, gg = tid & 63;
    float acc = 0.f;
#pragma unroll 8
    for (int d = 0; d < 64; d++)
        acc += sx[h*64 + d] * sWs[d*64 + gg];
    WcatT[(size_t)tid * 512 + cr] = __float2half_rn(acc * sit[h]);

    if (blockIdx.x == 0) {
        float acc2 = bslice[gg];
        for (int d = 0; d < 64; d++)
            acc2 += bx[h*64 + d] * sWs[d*64 + gg];
        bcomb[tid] = acc2 * sit[h];
    }
}

// ============================================================
// FP16 GEMM 128x128x32, 8 warps (warp tile 32x64), 4-stage cp.async,
// ldmatrix fragment loads, register-resident softmax epilogue.
// ============================================================
#define AH 40     // padded k-stride (halves), 80B rows
#define STG_BYTES 10240
#define SM_GEMM (8 * STG_BYTES)   // 81920

template<int MODE>
__global__ __launch_bounds__(256, 2) void f16_gemm(
    const __half* __restrict__ A, const __half* __restrict__ BT,
    const float* __restrict__ biasA, const float* __restrict__ biasB,
    __half* __restrict__ wOut, __half* __restrict__ fxOut,
    float* __restrict__ outF, float* __restrict__ npart,
    int K, int bRowsPerBatch, int bMatStride)
{
    extern __shared__ char smem[];

    const int tid  = threadIdx.x;
    const int lane = tid & 31;
    const int warp = tid >> 5;
    const int wr   = warp >> 1;
    const int wc   = warp & 1;
    const int row0 = blockIdx.y * 128;
    const int col0 = blockIdx.x * 128;

    const __half* Bp = BT;
    if (bRowsPerBatch) Bp += (size_t)(row0 / bRowsPerBatch) * (size_t)bMatStride;

    float c[2][8][4];
#pragma unroll
    for (int i = 0; i < 2; i++)
#pragma unroll
        for (int j = 0; j < 8; j++)
#pragma unroll
            for (int r = 0; r < 4; r++) c[i][j][r] = 0.f;

    const int g = lane >> 2;
    const int t = lane & 3;

    const uint32_t As0 = (uint32_t)__cvta_generic_to_shared(smem);
    const uint32_t Bs0 = As0 + 4 * STG_BYTES;
    uint32_t aOff[2], bOff[4];
#pragma unroll
    for (int i = 0; i < 2; i++)
        aOff[i] = (uint32_t)(((wr*32 + i*16 + (lane & 15)) * AH + ((lane >> 4) << 3)) * 2);
#pragma unroll
    for (int jp = 0; jp < 4; jp++)
        bOff[jp] = (uint32_t)(((wc*64 + jp*16 + ((lane >> 4) << 3) + (lane & 7)) * AH
                               + (((lane >> 3) & 1) << 3)) * 2);

    const int sr  = tid >> 2;
    const int skc = (tid & 3) * 8;

    auto stage = [&](int kt, int buf) {
        __half* a = (__half*)(smem + buf * STG_BYTES);
        __half* b = (__half*)(smem + 4 * STG_BYTES + buf * STG_BYTES);
        const int k0 = kt << 5;
#pragma unroll
        for (int it = 0; it < 2; it++) {
            int r = sr + it * 64;
            cp16(&a[r * AH + skc], A  + (size_t)(row0 + r) * K + k0 + skc);
            cp16(&b[r * AH + skc], Bp + (size_t)(col0 + r) * K + k0 + skc);
        }
    };

    const int ntiles = K >> 5;
    stage(0, 0); asm volatile("cp.async.commit_group;");
    stage(1, 1); asm volatile("cp.async.commit_group;");
    stage(2, 2); asm volatile("cp.async.commit_group;");

    for (int kt = 0; kt < ntiles; kt++) {
        asm volatile("cp.async.wait_group 2;");
        __syncthreads();
        if (kt + 3 < ntiles) stage(kt + 3, (kt + 3) & 3);
        asm volatile("cp.async.commit_group;");

        const uint32_t aBuf = As0 + (kt & 3) * STG_BYTES;
        const uint32_t bBuf = Bs0 + (kt & 3) * STG_BYTES;
#pragma unroll
        for (int ks = 0; ks < 2; ks++) {
            const uint32_t kbB = ks * 32;
            unsigned a[2][4], b[8][2];
#pragma unroll
            for (int i = 0; i < 2; i++)
                LDSM4(a[i][0], a[i][1], a[i][2], a[i][3], aBuf + aOff[i] + kbB);
#pragma unroll
            for (int jp = 0; jp < 4; jp++)
                LDSM4(b[jp*2][0], b[jp*2][1], b[jp*2+1][0], b[jp*2+1][1],
                      bBuf + bOff[jp] + kbB);
#pragma unroll
            for (int i = 0; i < 2; i++)
#pragma unroll
                for (int j = 0; j < 8; j++)
                    mma_f16(c[i][j], a[i], b[j]);
        }
        __syncthreads();
    }

    if (MODE == 1 && col0 < 512) {
        const int colbase = col0 + wc * 64;
        float bv[16];
#pragma unroll
        for (int j = 0; j < 8; j++) {
            bv[j*2]   = biasA[colbase + j*8 + t*2];
            bv[j*2+1] = biasA[colbase + j*8 + t*2 + 1];
        }
#pragma unroll
        for (int i = 0; i < 2; i++)
#pragma unroll
            for (int j = 0; j < 8; j++) {
                c[i][j][0] += bv[j*2];   c[i][j][1] += bv[j*2+1];
                c[i][j][2] += bv[j*2];   c[i][j][3] += bv[j*2+1];
            }

        float cs[16];
#pragma unroll
        for (int m = 0; m < 16; m++) cs[m] = 0.f;

#pragma unroll
        for (int i = 0; i < 2; i++)
#pragma unroll
            for (int h2 = 0; h2 < 2; h2++) {
                float mx = -1e30f;
#pragma unroll
                for (int j = 0; j < 8; j++)
                    mx = fmaxf(mx, fmaxf(c[i][j][h2*2], c[i][j][h2*2+1]));
                mx = fmaxf(mx, __shfl_xor_sync(0xffffffffu, mx, 1));
                mx = fmaxf(mx, __shfl_xor_sync(0xffffffffu, mx, 2));
                float s = 0.f;
#pragma unroll
                for (int j = 0; j < 8; j++) {
                    float e0 = __expf(c[i][j][h2*2]   - mx);
                    float e1 = __expf(c[i][j][h2*2+1] - mx);
                    c[i][j][h2*2] = e0; c[i][j][h2*2+1] = e1;
                    s += e0 + e1;
                }
                s += __shfl_xor_sync(0xffffffffu, s, 1);
                s += __shfl_xor_sync(0xffffffffu, s, 2);
                const float is = 1.0f / s;
                const size_t row = (size_t)(row0 + wr*32 + i*16 + h2*8 + g);
#pragma unroll
                for (int j = 0; j < 8; j++) {
                    __half2 h = __floats2half2_rn(c[i][j][h2*2]*is, c[i][j][h2*2+1]*is);
                    *(__half2*)(wOut + row * 512 + colbase + j*8 + t*2) = h;
                    float2 f = __half22float2(h);
                    cs[j*2] += f.x; cs[j*2+1] += f.y;
                }
            }

#pragma unroll
        for (int m = 0; m < 16; m++) {
            cs[m] += __shfl_xor_sync(0xffffffffu, cs[m], 4);
            cs[m] += __shfl_xor_sync(0xffffffffu, cs[m], 8);
            cs[m] += __shfl_xor_sync(0xffffffffu, cs[m], 16);
        }
        float* npsum = (float*)smem;
        if (lane < 4) {
#pragma unroll
            for (int j = 0; j < 8; j++) {
                npsum[wr*128 + wc*64 + j*8 + lane*2]     = cs[j*2];
                npsum[wr*128 + wc*64 + j*8 + lane*2 + 1] = cs[j*2+1];
            }
        }
        __syncthreads();
        if (tid < 128)
            npart[(size_t)blockIdx.y * 512 + col0 + tid] =
                npsum[tid] + npsum[128+tid] + npsum[256+tid] + npsum[384+tid];
    } else if (MODE == 1) {
        const int cg = col0 - 512 + wc * 64;
#pragma unroll
        for (int i = 0; i < 2; i++) {
            int rm = row0 + wr*32 + i*16 + g;
#pragma unroll
            for (int j = 0; j < 8; j++) {
                int cn = cg + j*8 + t*2;
                float b0 = biasB[cn], b1 = biasB[cn + 1];
                *(__half2*)(fxOut + (size_t)rm * 512 + cn) =
                    __floats2half2_rn(c[i][j][0] + b0, c[i][j][1] + b1);
                *(__half2*)(fxOut + (size_t)(rm + 8) * 512 + cn) =
                    __floats2half2_rn(c[i][j][2] + b0, c[i][j][3] + b1);
            }
        }
    } else {
        const int cg = col0 + wc * 64;
#pragma unroll
        for (int i = 0; i < 2; i++) {
            int rm = row0 + wr*32 + i*16 + g;
#pragma unroll
            for (int j = 0; j < 8; j++) {
                int cn = cg + j*8 + t*2;
                float b0 = biasA[cn], b1 = biasA[cn + 1];
                *(float2*)(outF + (size_t)rm * 512 + cn) =
                    make_float2(c[i][j][0] + b0, c[i][j][1] + b1);
                *(float2*)(outF + (size_t)(rm + 8) * 512 + cn) =
                    make_float2(c[i][j][2] + b0, c[i][j][3] + b1);
            }
        }
    }
}

// ============================================================
// norm stage 1: np2[b*16+rbg][hg] = sum of 16 row-blocks (coalesced)
// ============================================================
__global__ __launch_bounds__(512) void norm_stage1_kernel(
    const float* __restrict__ npart, float* __restrict__ np2)
{
    const int b   = blockIdx.x >> 4;
    const int rbg = blockIdx.x & 15;
    const int hg  = threadIdx.x;
    float s = 0.f;
#pragma unroll
    for (int rb = 0; rb < 16; rb++)
        s += npart[((size_t)(b * 256 + rbg * 16 + rb)) * 512 + hg];
    np2[(size_t)blockIdx.x * 512 + hg] = s;
}

// ============================================================
// fused reduce: blocks [0,256) = tok partial sums; [256,260) = norm stage 2
// ============================================================
__global__ void reduce_kernel(const float* __restrict__ part,
                              float* __restrict__ tok,
                              const float* __restrict__ np2,
                              float* __restrict__ norm)
{
    const int blk = blockIdx.x;
    if (blk < 256) {
        int idx = blk * 256 + threadIdx.x;
        int bh = idx >> 12, gd = idx & 4095;
        float s = 0.f;
#pragma unroll
        for (int c = 0; c < TOK_CHUNKS; c++)
            s += part[((size_t)bh * TOK_CHUNKS + c) * 4096 + gd];
        tok[idx] = s;
    } else {
        int e = (blk - 256) * 256 + threadIdx.x;   // 0..1023
        int b = e >> 9, hg = e & 511;
        float s = 0.f;
#pragma unroll
        for (int c = 0; c < 16; c++)
            s += np2[((size_t)(b * 16 + c)) * 512 + hg];
        norm[e] = s;
    }
}

// ============================================================
// tokens partials via tensor cores (128-token tiles, R11 version)
// ============================================================
#define WT 72
#define TPT_TILE_H (128 * WT)
#define TPT_SMEM (4 * TPT_TILE_H * 2)

__global__ __launch_bounds__(256) void tokpart_mma_kernel(
    const __half* __restrict__ fx, const __half* __restrict__ w,
    float* __restrict__ part)
{
    extern __shared__ char smem[];
    const int chunk = blockIdx.x;
    const int bh = blockIdx.y;
    const int b = bh >> 3, h = bh & 7;
    const size_t rbase = (size_t)b * NN + (size_t)chunk * 2048;

    const int tid  = threadIdx.x;
    const int lane = tid & 31;
    const int warp = tid >> 5;
    const int wm   = warp >> 1;
    const int wn   = warp & 1;

    const uint32_t S0 = (uint32_t)__cvta_generic_to_shared(smem);

    float c[4][4];
#pragma unroll
    for (int nj = 0; nj < 4; nj++)
#pragma unroll
        for (int r = 0; r < 4; r++) c[nj][r] = 0.f;

    const uint32_t aOff = (uint32_t)(((((lane >> 4) << 3) + (lane & 7)) * WT
                           + wm*16 + (((lane >> 3) & 1) << 3)) * 2);
    uint32_t bOff[2];
#pragma unroll
    for (int p2 = 0; p2 < 2; p2++)
        bOff[p2] = (uint32_t)((((((lane >> 3) & 1) << 3) + (lane & 7)) * WT
                    + wn*32 + p2*16 + ((lane >> 4) << 3)) * 2);

    auto stage = [&](int kt, int buf) {
        __half* wsb = (__half*)smem + buf * TPT_TILE_H;
        __half* fsb = (__half*)smem + 2 * TPT_TILE_H + buf * TPT_TILE_H;
#pragma unroll
        for (int it = 0; it < 4; it++) {
            int s = tid + it * 256;
            int r = s >> 3;
            int c8 = (s & 7) * 8;
            size_t row = rbase + (size_t)kt * 128 + r;
            cp16(&wsb[r * WT + c8], w  + row * 512 + h * 64 + c8);
            cp16(&fsb[r * WT + c8], fx + row * 512 + h * 64 + c8);
        }
    };

    stage(0, 0);
    asm volatile("cp.async.commit_group;");

    for (int kt = 0; kt < 16; kt++) {
        asm volatile("cp.async.wait_group 0;");
        __syncthreads();
        if (kt + 1 < 16) {
            stage(kt + 1, (kt + 1) & 1);
            asm volatile("cp.async.commit_group;");
        }
        const int buf = kt & 1;
        const uint32_t wBuf = S0 + buf * TPT_TILE_H * 2;
        const uint32_t fBuf = S0 + (2 + buf) * TPT_TILE_H * 2;
#pragma unroll
        for (int ks = 0; ks < 8; ks++) {
            const uint32_t ksB = (uint32_t)(ks * 16 * WT * 2);
            unsigned a[4], bb[4][2];
            LDSM4T(a[0], a[1], a[2], a[3], wBuf + aOff + ksB);
            LDSM4T(bb[0][0], bb[0][1], bb[1][0], bb[1][1], fBuf + bOff[0] + ksB);
            LDSM4T(bb[2][0], bb[2][1], bb[3][0], bb[3][1], fBuf + bOff[1] + ksB);
#pragma unroll
            for (int nj = 0; nj < 4; nj++)
                mma_f16(c[nj], a, bb[nj]);
        }
        __syncthreads();
    }

    const int g4 = lane >> 2;
    const int t  = lane & 3;
    float* p = part + ((size_t)bh * TOK_CHUNKS + chunk) * 4096;
#pragma unroll
    for (int nj = 0; nj < 4; nj++) {
        int col = wn*32 + nj*8 + t*2;
        *(float2*)&p[(wm*16 + g4) * 64 + col]     = make_float2(c[nj][0], c[nj][1]);
        *(float2*)&p[(wm*16 + g4 + 8) * 64 + col] = make_float2(c[nj][2], c[nj][3]);
    }
}

// ============================================================
// tiny attention (R11 version: ck/cv computed in-kernel)
// ============================================================
template<int NC>
__device__ __forceinline__ void row_gemm_cols(
    const float* __restrict__ xrow, int Kd,
    const float* __restrict__ W, const float* __restrict__ bias,
    float* __restrict__ outp, int c0)
{
    float acc[NC];
#pragma unroll
    for (int j = 0; j < NC; j++) acc[j] = bias[c0 + j];
    for (int d = 0; d < Kd; d++) {
        float xv = xrow[d];
        const float4* W4 = (const float4*)(W + (size_t)d * 64 + c0);
#pragma unroll
        for (int j4 = 0; j4 < NC/4; j4++) {
            float4 wv = W4[j4];
            acc[j4*4+0] += xv*wv.x; acc[j4*4+1] += xv*wv.y;
            acc[j4*4+2] += xv*wv.z; acc[j4*4+3] += xv*wv.w;
        }
    }
#pragma unroll
    for (int j = 0; j < NC; j++) outp[c0 + j] = acc[j];
}

__device__ __forceinline__ void attn_row(
    const float* __restrict__ qrow, const float* __restrict__ Kt,
    const float* __restrict__ Vt, float* __restrict__ o)
{
    float qr[64];
#pragma unroll
    for (int d = 0; d < 64; d++) qr[d] = qrow[d];
    float sc[64];
    float m = -1e30f;
    for (int j = 0; j < 64; j++) {
        const float4* kr = (const float4*)(Kt + j * 64);
        float a = 0.f;
#pragma unroll
        for (int d4 = 0; d4 < 16; d4++) {
            float4 kv = kr[d4];
            a += qr[d4*4]*kv.x + qr[d4*4+1]*kv.y + qr[d4*4+2]*kv.z + qr[d4*4+3]*kv.w;
        }
        sc[j] = a * 0.125f;
        m = fmaxf(m, sc[j]);
    }
    float s = 0.f;
#pragma unroll
    for (int j = 0; j < 64; j++) { sc[j] = expf(sc[j] - m); s += sc[j]; }
    float is = 1.0f / s;
#pragma unroll
    for (int d = 0; d < 64; d++) o[d] = 0.f;
    for (int j = 0; j < 64; j++) {
        float p = sc[j] * is;
        const float4* vr = (const float4*)(Vt + j * 64);
#pragma unroll
        for (int d4 = 0; d4 < 16; d4++) {
            float4 vv = vr[d4];
            o[d4*4+0] += p*vv.x; o[d4*4+1] += p*vv.y;
            o[d4*4+2] += p*vv.z; o[d4*4+3] += p*vv.w;
        }
    }
}

__global__ __launch_bounds__(256) void attn_kernel(
    const float* __restrict__ ctx,
    const float* __restrict__ Wq, const float* __restrict__ bq,
    const float* __restrict__ Wk, const float* __restrict__ bk,
    const float* __restrict__ Wv, const float* __restrict__ bv,
    const float* __restrict__ Wcq, const float* __restrict__ bcq,
    const float* __restrict__ Wck, const float* __restrict__ bck,
    const float* __restrict__ Wcv, const float* __restrict__ bcv,
    const float* __restrict__ smix,
    const float* __restrict__ tokens, const float* __restrict__ norm,
    float* __restrict__ ot)
{
    extern __shared__ float sm[];
    float* s_tok = sm;
    float* s_q   = sm + 4096;
    float* s_k   = sm + 2*4096;
    float* s_v   = sm + 3*4096;
    float* s_cq  = sm + 4*4096;
    float* s_ck  = sm + 5*4096;
    float* s_cv  = sm + 6*4096;

    const int bh = blockIdx.x;
    const int tid = threadIdx.x;

    for (int idx = tid; idx < 4096; idx += 256) {
        int row = idx >> 6;
        float inv = 1.0f / (norm[bh*64 + row] + EPS);
        s_tok[idx] = tokens[(size_t)bh*4096 + idx] * inv;
    }
    __syncthreads();

    {
        const int pid = tid >> 6;
        const int i   = tid & 63;
        const float* W; const float* bb; float* dst;
        if (pid == 0)      { W = Wq;  bb = bq;  dst = s_q;  }
        else if (pid == 1) { W = Wk;  bb = bk;  dst = s_k;  }
        else if (pid == 2) { W = Wv;  bb = bv;  dst = s_v;  }
        else               { W = Wcq; bb = bcq; dst = s_cq; }
        row_gemm_cols<64>(&s_tok[i*64], 64, W, bb, &dst[i*64], 0);
    }
    {
        const int mat = tid >> 7;
        const int sub = tid & 127;
        const int i   = sub >> 1;
        const int c0  = (sub & 1) * 32;
        const float* crow = ctx + ((size_t)bh*64 + i) * 256;
        if (mat == 0) row_gemm_cols<32>(crow, 256, Wck, bck, &s_ck[i*64], c0);
        else          row_gemm_cols<32>(crow, 256, Wcv, bcv, &s_cv[i*64], c0);
    }
    __syncthreads();

    if (tid < 64) {
        float o[64];
        attn_row(&s_q[tid*64], s_k, s_v, o);
#pragma unroll
        for (int d = 0; d < 64; d++) s_tok[tid*64 + d] = o[d];
    } else if (tid < 128) {
        const int i = tid - 64;
        float o[64];
        attn_row(&s_cq[i*64], s_ck, s_cv, o);
#pragma unroll
        for (int d = 0; d < 64; d++) s_cq[i*64 + d] = o[d];
    }
    __syncthreads();

    const float gmix = 1.0f / (1.0f + expf(-smix[0]));
    for (int idx = tid; idx < 4096; idx += 256)
        ot[(size_t)bh*4096 + idx] = gmix * s_tok[idx] + (1.0f - gmix) * s_cq[idx];
}

// ============================================================
// M^T[b][c][hg] = sum_d out_tok[b,hg,d] * Wo[h*64+d, c]  (fp16 out)
// ============================================================
__global__ __launch_bounds__(256) void m_kernel(
    const float* __restrict__ Wo, const float* __restrict__ ot,
    __half* __restrict__ MT)
{
    __shared__ float s_ot[4096];
    __shared__ float s_wo[64 * 128];
    const int bh = blockIdx.y;
    const int h = bh & 7, b = bh >> 3;
    const int c0 = blockIdx.x * 128;
    const int tid = threadIdx.x;

    for (int idx = tid; idx < 1024; idx += 256)
        ((float4*)s_ot)[idx] = ((const float4*)(ot + (size_t)bh * 4096))[idx];
    for (int idx = tid; idx < 2048; idx += 256) {
        int d = idx >> 5;
        int c4 = idx & 31;
        ((float4*)s_wo)[idx] = *(const float4*)(Wo + (size_t)(h*64 + d)*512 + c0 + c4*4);
    }
    __syncthreads();

    const int g0 = (tid >> 3) * 2;
    const int ct = (tid & 7) * 16;
    float acc[2][16];
#pragma unroll
    for (int g = 0; g < 2; g++)
#pragma unroll
        for (int c = 0; c < 16; c++) acc[g][c] = 0.f;

    for (int d = 0; d < 64; d++) {
        float a0 = s_ot[g0*64 + d];
        float a1 = s_ot[(g0+1)*64 + d];
#pragma unroll
        for (int c4 = 0; c4 < 4; c4++) {
            float4 wv = *(const float4*)&s_wo[d*128 + ct + c4*4];
            acc[0][c4*4+0]+=a0*wv.x; acc[0][c4*4+1]+=a0*wv.y; acc[0][c4*4+2]+=a0*wv.z; acc[0][c4*4+3]+=a0*wv.w;
            acc[1][c4*4+0]+=a1*wv.x; acc[1][c4*4+1]+=a1*wv.y; acc[1][c4*4+2]+=a1*wv.z; acc[1][c4*4+3]+=a1*wv.w;
        }
    }

#pragma unroll
    for (int g = 0; g < 2; g++) {
        int hg = h*64 + g0 + g;
#pragma unroll
        for (int c = 0; c < 16; c++)
            MT[(size_t)b * 262144 + (size_t)(c0 + ct + c) * 512 + hg] =
                __float2half_rn(acc[g][c]);
    }
}

// ============================================================
// host launcher
// ============================================================
extern "C" void kernel_launch(void* const* d_in, const int* in_sizes, int n_in,
                              void* d_out, int out_size)
{
    const float* x      = (const float*)d_in[0];
    const float* ctx    = (const float*)d_in[1];
    const float* Wx     = (const float*)d_in[2];
    const float* bx     = (const float*)d_in[3];
    const float* Wfx    = (const float*)d_in[4];
    const float* bfx    = (const float*)d_in[5];
    const float* Wslice = (const float*)d_in[6];
    const float* bslice = (const float*)d_in[7];
    const float* temp   = (const float*)d_in[8];
    const float* Wq     = (const float*)d_in[9];
    const float* bq     = (const float*)d_in[10];
    const float* Wk     = (const float*)d_in[11];
    const float* bk     = (const float*)d_in[12];
    const float* Wv     = (const float*)d_in[13];
    const float* bv     = (const float*)d_in[14];
    const float* Wcq    = (const float*)d_in[15];
    const float* bcq    = (const float*)d_in[16];
    const float* Wck    = (const float*)d_in[17];
    const float* bck    = (const float*)d_in[18];
    const float* Wcv    = (const float*)d_in[19];
    const float* bcv    = (const float*)d_in[20];
    const float* smix   = (const float*)d_in[21];
    const float* Wo     = (const float*)d_in[22];
    const float* bo     = (const float*)d_in[23];
    float* out = (float*)d_out;

    void *p;
    cudaGetSymbolAddress(&p, g_xh);    __half* xh    = (__half*)p;
    cudaGetSymbolAddress(&p, g_wh);    __half* wh    = (__half*)p;
    cudaGetSymbolAddress(&p, g_fxh);   __half* fxh   = (__half*)p;
    cudaGetSymbolAddress(&p, g_npart); float* npart  = (float*)p;
    cudaGetSymbolAddress(&p, g_np2);   float* np2    = (float*)p;
    cudaGetSymbolAddress(&p, g_norm);  float* norm   = (float*)p;
    cudaGetSymbolAddress(&p, g_tpart); float* tpart  = (float*)p;
    cudaGetSymbolAddress(&p, g_tok);   float* tok    = (float*)p;
    cudaGetSymbolAddress(&p, g_ot);    float* ot     = (float*)p;
    cudaGetSymbolAddress(&p, g_MTh);   __half* MTh   = (__half*)p;
    cudaGetSymbolAddress(&p, g_WcatTh);__half* WcatT = (__half*)p;
    cudaGetSymbolAddress(&p, g_bcomb); float* bcomb  = (float*)p;

    cudaFuncSetAttribute(f16_gemm<1>, cudaFuncAttributeMaxDynamicSharedMemorySize, SM_GEMM);
    cudaFuncSetAttribute(f16_gemm<0>, cudaFuncAttributeMaxDynamicSharedMemorySize, SM_GEMM);
    cudaFuncSetAttribute(tokpart_mma_kernel, cudaFuncAttributeMaxDynamicSharedMemorySize, TPT_SMEM);
    cudaFuncSetAttribute(attn_kernel, cudaFuncAttributeMaxDynamicSharedMemorySize, 7*4096*4);

    // 0: x -> fp16; assemble WcatT^T fp16; bcomb
    round_f16_kernel<<<2048, 256>>>(x, xh, ROWS*CC/4);
    wfx_cat_kernel<<<1024, 256>>>(Wfx, WcatT);
    wcomb_kernel<<<512, 512>>>(Wx, Wslice, temp, bx, bslice, WcatT, bcomb);
    // 1: merged fp16 GEMM: softmax->wh(+npart) | bias->fxh
    f16_gemm<1><<<dim3(8, 512), 256, SM_GEMM>>>(
        xh, WcatT, bcomb, bfx, wh, fxh, nullptr, npart, CC, 0, 0);
    // 2: norm stage 1 (parallel, coalesced)
    norm_stage1_kernel<<<32, 512>>>(npart, np2);
    // 3: tokens = w^T @ fx (tensor cores)
    tokpart_mma_kernel<<<dim3(TOK_CHUNKS, 16), 256, TPT_SMEM>>>(fxh, wh, tpart);
    // 4: fused reduce (tok partials + norm stage 2)
    reduce_kernel<<<260, 256>>>(tpart, tok, np2, norm);
    // 5: tiny attention
    attn_kernel<<<16, 256, 7*4096*4>>>(ctx, Wq, bq, Wk, bk, Wv, bv,
                                       Wcq, bcq, Wck, bck, Wcv, bcv,
                                       smix, tok, norm, ot);
    // 6: fold out_tok @ Wo -> M^T (fp16)
    m_kernel<<<dim3(4, 16), 256>>>(Wo, ot, MTh);
    // 7: out = w @ M[b] + bo (fp16 GEMM, B per-batch)
    f16_gemm<0><<<dim3(4, 512), 256, SM_GEMM>>>(
        wh, MTh, bo, nullptr, nullptr, nullptr, out, nullptr, INNER, NN, 512*512);
}

// round 14
// speedup vs baseline: 1.1120x; 1.0098x over previous
#include <cuda_runtime.h>
#include <cuda_fp16.h>
#include <math.h>
#include <stdint.h>

// ---------------- problem constants ----------------
#define BB 2
#define NN 32768
#define CC 512
#define HH 8
#define DH 64
#define GG 64
#define CD 256
#define ROWS (BB*NN)          // 65536
#define INNER (HH*DH)         // 512
#define EPS 1e-5f
#define TOK_CHUNKS 16

// ---------------- scratch ----------------
__device__ __half g_xh   [ROWS * CC];
__device__ __half g_wh   [ROWS * INNER];
__device__ __half g_fxh  [ROWS * INNER];
__device__ float  g_npart[512 * 512];
__device__ float  g_np2  [32 * 512];
__device__ float  g_tpart[16 * TOK_CHUNKS * 4096];
__device__ float  g_ot   [16 * 4096];
__device__ __half g_MTh  [BB * 512 * 512];
__device__ __half g_WcatTh[1024 * 512];
__device__ float  g_bcomb[512];

// ---------------- helpers ----------------
__device__ __forceinline__ void cp16(void* dst, const void* src) {
    unsigned d = (unsigned)__cvta_generic_to_shared(dst);
    asm volatile("cp.async.cg.shared.global [%0], [%1], 16;" :: "r"(d), "l"(src));
}
__device__ __forceinline__ void mma_f16(float* c, const unsigned* a, const unsigned* b) {
    asm volatile(
        "mma.sync.aligned.m16n8k16.row.col.f32.f16.f16.f32 "
        "{%0,%1,%2,%3},{%4,%5,%6,%7},{%8,%9},{%0,%1,%2,%3};"
        : "+f"(c[0]), "+f"(c[1]), "+f"(c[2]), "+f"(c[3])
        : "r"(a[0]), "r"(a[1]), "r"(a[2]), "r"(a[3]), "r"(b[0]), "r"(b[1]));
}
#define LDSM4(r0, r1, r2, r3, addr) \
    asm volatile("ldmatrix.sync.aligned.m8n8.x4.shared.b16 {%0,%1,%2,%3}, [%4];" \
        : "=r"(r0), "=r"(r1), "=r"(r2), "=r"(r3) : "r"(addr))
#define LDSM4T(r0, r1, r2, r3, addr) \
    asm volatile("ldmatrix.sync.aligned.m8n8.x4.trans.shared.b16 {%0,%1,%2,%3}, [%4];" \
        : "=r"(r0), "=r"(r1), "=r"(r2), "=r"(r3) : "r"(addr))

// ============================================================
// fused prologue (block-range dispatch)
//   [0, 2048):      x fp32 -> xh fp16 (grid-stride)
//   [2048, 3072):   Wfx -> WcatT rows 512..1023 (transposed fp16)
//   [3072, 3584):   Wcomb -> WcatT rows 0..511 (+bcomb in block 3072)
// ============================================================
#define ROUND_BLKS 2048
#define WFX_BLKS 1024
#define WCOMB_BLKS 512
#define PREP_BLKS (ROUND_BLKS + WFX_BLKS + WCOMB_BLKS)

__global__ __launch_bounds__(256) void prep_kernel(
    const float* __restrict__ x, __half* __restrict__ xh,
    const float* __restrict__ Wfx,
    const float* __restrict__ Wx, const float* __restrict__ Wslice,
    const float* __restrict__ temp,
    const float* __restrict__ bx, const float* __restrict__ bslice,
    __half* __restrict__ WcatT, float* __restrict__ bcomb)
{
    const int tid = threadIdx.x;
    const int blk = blockIdx.x;

    if (blk < ROUND_BLKS) {
        const int n4 = ROWS * CC / 4;
        int idx = blk * 256 + tid;
        const int stride = ROUND_BLKS * 256;
        for (; idx < n4; idx += stride) {
            float4 v = ((const float4*)x)[idx];
            __half2* o = (__half2*)xh + idx * 2;
            o[0] = __floats2half2_rn(v.x, v.y);
            o[1] = __floats2half2_rn(v.z, v.w);
        }
    } else if (blk < ROUND_BLKS + WFX_BLKS) {
        int idx = (blk - ROUND_BLKS) * 256 + tid;
        int k = idx >> 9;
        int n = idx & 511;
        WcatT[(size_t)(512 + n) * 512 + k] = __float2half_rn(Wfx[(size_t)k * 512 + n]);
    } else {
        __shared__ float sWs[4096];
        __shared__ float sx[512];
        __shared__ float sit[8];
        const int cr = blk - (ROUND_BLKS + WFX_BLKS);
        for (int i = tid; i < 4096; i += 256) sWs[i] = Wslice[i];
        sx[tid] = Wx[(size_t)cr * 512 + tid];
        sx[tid + 256] = Wx[(size_t)cr * 512 + tid + 256];
        if (tid < 8) {
            float tv = temp[tid];
            sit[tid] = 1.0f / fminf(fmaxf(tv, 0.1f), 5.0f);
        }
        __syncthreads();
#pragma unroll
        for (int rep = 0; rep < 2; rep++) {
            const int o = tid + rep * 256;
            const int h = o >> 6, gg = o & 63;
            float acc = 0.f;
#pragma unroll 8
            for (int d = 0; d < 64; d++)
                acc += sx[h*64 + d] * sWs[d*64 + gg];
            WcatT[(size_t)o * 512 + cr] = __float2half_rn(acc * sit[h]);
            if (cr == 0) {
                float acc2 = bslice[gg];
                for (int d = 0; d < 64; d++)
                    acc2 += bx[h*64 + d] * sWs[d*64 + gg];
                bcomb[o] = acc2 * sit[h];
            }
        }
    }
}

// ============================================================
// FP16 GEMM 128x128x32, 8 warps (warp tile 32x64), 4-stage cp.async,
// ldmatrix fragment loads, register-resident softmax epilogue.
// ============================================================
#define AH 40
#define STG_BYTES 10240
#define SM_GEMM (8 * STG_BYTES)

template<int MODE>
__global__ __launch_bounds__(256, 2) void f16_gemm(
    const __half* __restrict__ A, const __half* __restrict__ BT,
    const float* __restrict__ biasA, const float* __restrict__ biasB,
    __half* __restrict__ wOut, __half* __restrict__ fxOut,
    float* __restrict__ outF, float* __restrict__ npart,
    int K, int bRowsPerBatch, int bMatStride)
{
    extern __shared__ char smem[];

    const int tid  = threadIdx.x;
    const int lane = tid & 31;
    const int warp = tid >> 5;
    const int wr   = warp >> 1;
    const int wc   = warp & 1;
    const int row0 = blockIdx.y * 128;
    const int col0 = blockIdx.x * 128;

    const __half* Bp = BT;
    if (bRowsPerBatch) Bp += (size_t)(row0 / bRowsPerBatch) * (size_t)bMatStride;

    float c[2][8][4];
#pragma unroll
    for (int i = 0; i < 2; i++)
#pragma unroll
        for (int j = 0; j < 8; j++)
#pragma unroll
            for (int r = 0; r < 4; r++) c[i][j][r] = 0.f;

    const int g = lane >> 2;
    const int t = lane & 3;

    const uint32_t As0 = (uint32_t)__cvta_generic_to_shared(smem);
    const uint32_t Bs0 = As0 + 4 * STG_BYTES;
    uint32_t aOff[2], bOff[4];
#pragma unroll
    for (int i = 0; i < 2; i++)
        aOff[i] = (uint32_t)(((wr*32 + i*16 + (lane & 15)) * AH + ((lane >> 4) << 3)) * 2);
#pragma unroll
    for (int jp = 0; jp < 4; jp++)
        bOff[jp] = (uint32_t)(((wc*64 + jp*16 + ((lane >> 4) << 3) + (lane & 7)) * AH
                               + (((lane >> 3) & 1) << 3)) * 2);

    const int sr  = tid >> 2;
    const int skc = (tid & 3) * 8;

    auto stage = [&](int kt, int buf) {
        __half* a = (__half*)(smem + buf * STG_BYTES);
        __half* b = (__half*)(smem + 4 * STG_BYTES + buf * STG_BYTES);
        const int k0 = kt << 5;
#pragma unroll
        for (int it = 0; it < 2; it++) {
            int r = sr + it * 64;
            cp16(&a[r * AH + skc], A  + (size_t)(row0 + r) * K + k0 + skc);
            cp16(&b[r * AH + skc], Bp + (size_t)(col0 + r) * K + k0 + skc);
        }
    };

    const int ntiles = K >> 5;
    stage(0, 0); asm volatile("cp.async.commit_group;");
    stage(1, 1); asm volatile("cp.async.commit_group;");
    stage(2, 2); asm volatile("cp.async.commit_group;");

    for (int kt = 0; kt < ntiles; kt++) {
        asm volatile("cp.async.wait_group 2;");
        __syncthreads();
        if (kt + 3 < ntiles) stage(kt + 3, (kt + 3) & 3);
        asm volatile("cp.async.commit_group;");

        const uint32_t aBuf = As0 + (kt & 3) * STG_BYTES;
        const uint32_t bBuf = Bs0 + (kt & 3) * STG_BYTES;
#pragma unroll
        for (int ks = 0; ks < 2; ks++) {
            const uint32_t kbB = ks * 32;
            unsigned a[2][4], b[8][2];
#pragma unroll
            for (int i = 0; i < 2; i++)
                LDSM4(a[i][0], a[i][1], a[i][2], a[i][3], aBuf + aOff[i] + kbB);
#pragma unroll
            for (int jp = 0; jp < 4; jp++)
                LDSM4(b[jp*2][0], b[jp*2][1], b[jp*2+1][0], b[jp*2+1][1],
                      bBuf + bOff[jp] + kbB);
#pragma unroll
            for (int i = 0; i < 2; i++)
#pragma unroll
                for (int j = 0; j < 8; j++)
                    mma_f16(c[i][j], a[i], b[j]);
        }
        __syncthreads();
    }

    if (MODE == 1 && col0 < 512) {
        const int colbase = col0 + wc * 64;
        float bv[16];
#pragma unroll
        for (int j = 0; j < 8; j++) {
            bv[j*2]   = biasA[colbase + j*8 + t*2];
            bv[j*2+1] = biasA[colbase + j*8 + t*2 + 1];
        }
#pragma unroll
        for (int i = 0; i < 2; i++)
#pragma unroll
            for (int j = 0; j < 8; j++) {
                c[i][j][0] += bv[j*2];   c[i][j][1] += bv[j*2+1];
                c[i][j][2] += bv[j*2];   c[i][j][3] += bv[j*2+1];
            }

        float cs[16];
#pragma unroll
        for (int m = 0; m < 16; m++) cs[m] = 0.f;

#pragma unroll
        for (int i = 0; i < 2; i++)
#pragma unroll
            for (int h2 = 0; h2 < 2; h2++) {
                float mx = -1e30f;
#pragma unroll
                for (int j = 0; j < 8; j++)
                    mx = fmaxf(mx, fmaxf(c[i][j][h2*2], c[i][j][h2*2+1]));
                mx = fmaxf(mx, __shfl_xor_sync(0xffffffffu, mx, 1));
                mx = fmaxf(mx, __shfl_xor_sync(0xffffffffu, mx, 2));
                float s = 0.f;
#pragma unroll
                for (int j = 0; j < 8; j++) {
                    float e0 = __expf(c[i][j][h2*2]   - mx);
                    float e1 = __expf(c[i][j][h2*2+1] - mx);
                    c[i][j][h2*2] = e0; c[i][j][h2*2+1] = e1;
                    s += e0 + e1;
                }
                s += __shfl_xor_sync(0xffffffffu, s, 1);
                s += __shfl_xor_sync(0xffffffffu, s, 2);
                const float is = 1.0f / s;
                const size_t row = (size_t)(row0 + wr*32 + i*16 + h2*8 + g);
#pragma unroll
                for (int j = 0; j < 8; j++) {
                    __half2 h = __floats2half2_rn(c[i][j][h2*2]*is, c[i][j][h2*2+1]*is);
                    *(__half2*)(wOut + row * 512 + colbase + j*8 + t*2) = h;
                    float2 f = __half22float2(h);
                    cs[j*2] += f.x; cs[j*2+1] += f.y;
                }
            }

#pragma unroll
        for (int m = 0; m < 16; m++) {
            cs[m] += __shfl_xor_sync(0xffffffffu, cs[m], 4);
            cs[m] += __shfl_xor_sync(0xffffffffu, cs[m], 8);
            cs[m] += __shfl_xor_sync(0xffffffffu, cs[m], 16);
        }
        float* npsum = (float*)smem;
        if (lane < 4) {
#pragma unroll
            for (int j = 0; j < 8; j++) {
                npsum[wr*128 + wc*64 + j*8 + lane*2]     = cs[j*2];
                npsum[wr*128 + wc*64 + j*8 + lane*2 + 1] = cs[j*2+1];
            }
        }
        __syncthreads();
        if (tid < 128)
            npart[(size_t)blockIdx.y * 512 + col0 + tid] =
                npsum[tid] + npsum[128+tid] + npsum[256+tid] + npsum[384+tid];
    } else if (MODE == 1) {
        const int cg = col0 - 512 + wc * 64;
#pragma unroll
        for (int i = 0; i < 2; i++) {
            int rm = row0 + wr*32 + i*16 + g;
#pragma unroll
            for (int j = 0; j < 8; j++) {
                int cn = cg + j*8 + t*2;
                float b0 = biasB[cn], b1 = biasB[cn + 1];
                *(__half2*)(fxOut + (size_t)rm * 512 + cn) =
                    __floats2half2_rn(c[i][j][0] + b0, c[i][j][1] + b1);
                *(__half2*)(fxOut + (size_t)(rm + 8) * 512 + cn) =
                    __floats2half2_rn(c[i][j][2] + b0, c[i][j][3] + b1);
            }
        }
    } else {
        const int cg = col0 + wc * 64;
#pragma unroll
        for (int i = 0; i < 2; i++) {
            int rm = row0 + wr*32 + i*16 + g;
#pragma unroll
            for (int j = 0; j < 8; j++) {
                int cn = cg + j*8 + t*2;
                float b0 = biasA[cn], b1 = biasA[cn + 1];
                *(float2*)(outF + (size_t)rm * 512 + cn) =
                    make_float2(c[i][j][0] + b0, c[i][j][1] + b1);
                *(float2*)(outF + (size_t)(rm + 8) * 512 + cn) =
                    make_float2(c[i][j][2] + b0, c[i][j][3] + b1);
            }
        }
    }
}

// ============================================================
// norm stage 1: np2[b*16+rbg][hg] = sum of 16 row-blocks (coalesced)
// ============================================================
__global__ __launch_bounds__(512) void norm_stage1_kernel(
    const float* __restrict__ npart, float* __restrict__ np2)
{
    const int b   = blockIdx.x >> 4;
    const int rbg = blockIdx.x & 15;
    const int hg  = threadIdx.x;
    float s = 0.f;
#pragma unroll
    for (int rb = 0; rb < 16; rb++)
        s += npart[((size_t)(b * 256 + rbg * 16 + rb)) * 512 + hg];
    np2[(size_t)blockIdx.x * 512 + hg] = s;
}

// ============================================================
// tokens partials via tensor cores (128-token tiles, 2 CTA/SM)
// ============================================================
#define WT 72
#define TPT_TILE_H (128 * WT)
#define TPT_SMEM (4 * TPT_TILE_H * 2)

__global__ __launch_bounds__(256, 2) void tokpart_mma_kernel(
    const __half* __restrict__ fx, const __half* __restrict__ w,
    float* __restrict__ part)
{
    extern __shared__ char smem[];
    const int chunk = blockIdx.x;
    const int bh = blockIdx.y;
    const int b = bh >> 3, h = bh & 7;
    const size_t rbase = (size_t)b * NN + (size_t)chunk * 2048;

    const int tid  = threadIdx.x;
    const int lane = tid & 31;
    const int warp = tid >> 5;
    const int wm   = warp >> 1;
    const int wn   = warp & 1;

    const uint32_t S0 = (uint32_t)__cvta_generic_to_shared(smem);

    float c[4][4];
#pragma unroll
    for (int nj = 0; nj < 4; nj++)
#pragma unroll
        for (int r = 0; r < 4; r++) c[nj][r] = 0.f;

    const uint32_t aOff = (uint32_t)(((((lane >> 4) << 3) + (lane & 7)) * WT
                           + wm*16 + (((lane >> 3) & 1) << 3)) * 2);
    uint32_t bOff[2];
#pragma unroll
    for (int p2 = 0; p2 < 2; p2++)
        bOff[p2] = (uint32_t)((((((lane >> 3) & 1) << 3) + (lane & 7)) * WT
                    + wn*32 + p2*16 + ((lane >> 4) << 3)) * 2);

    auto stage = [&](int kt, int buf) {
        __half* wsb = (__half*)smem + buf * TPT_TILE_H;
        __half* fsb = (__half*)smem + 2 * TPT_TILE_H + buf * TPT_TILE_H;
#pragma unroll
        for (int it = 0; it < 4; it++) {
            int s = tid + it * 256;
            int r = s >> 3;
            int c8 = (s & 7) * 8;
            size_t row = rbase + (size_t)kt * 128 + r;
            cp16(&wsb[r * WT + c8], w  + row * 512 + h * 64 + c8);
            cp16(&fsb[r * WT + c8], fx + row * 512 + h * 64 + c8);
        }
    };

    stage(0, 0);
    asm volatile("cp.async.commit_group;");

    for (int kt = 0; kt < 16; kt++) {
        asm volatile("cp.async.wait_group 0;");
        __syncthreads();
        if (kt + 1 < 16) {
            stage(kt + 1, (kt + 1) & 1);
            asm volatile("cp.async.commit_group;");
        }
        const int buf = kt & 1;
        const uint32_t wBuf = S0 + buf * TPT_TILE_H * 2;
        const uint32_t fBuf = S0 + (2 + buf) * TPT_TILE_H * 2;
#pragma unroll
        for (int ks = 0; ks < 8; ks++) {
            const uint32_t ksB = (uint32_t)(ks * 16 * WT * 2);
            unsigned a[4], bb[4][2];
            LDSM4T(a[0], a[1], a[2], a[3], wBuf + aOff + ksB);
            LDSM4T(bb[0][0], bb[0][1], bb[1][0], bb[1][1], fBuf + bOff[0] + ksB);
            LDSM4T(bb[2][0], bb[2][1], bb[3][0], bb[3][1], fBuf + bOff[1] + ksB);
#pragma unroll
            for (int nj = 0; nj < 4; nj++)
                mma_f16(c[nj], a, bb[nj]);
        }
        __syncthreads();
    }

    const int g4 = lane >> 2;
    const int t  = lane & 3;
    float* p = part + ((size_t)bh * TOK_CHUNKS + chunk) * 4096;
#pragma unroll
    for (int nj = 0; nj < 4; nj++) {
        int col = wn*32 + nj*8 + t*2;
        *(float2*)&p[(wm*16 + g4) * 64 + col]     = make_float2(c[nj][0], c[nj][1]);
        *(float2*)&p[(wm*16 + g4 + 8) * 64 + col] = make_float2(c[nj][2], c[nj][3]);
    }
}

// ============================================================
// tiny attention — also performs the final tok/norm reductions
// ============================================================
template<int NC>
__device__ __forceinline__ void row_gemm_cols(
    const float* __restrict__ xrow, int Kd,
    const float* __restrict__ W, const float* __restrict__ bias,
    float* __restrict__ outp, int c0)
{
    float acc[NC];
#pragma unroll
    for (int j = 0; j < NC; j++) acc[j] = bias[c0 + j];
    for (int d = 0; d < Kd; d++) {
        float xv = xrow[d];
        const float4* W4 = (const float4*)(W + (size_t)d * 64 + c0);
#pragma unroll
        for (int j4 = 0; j4 < NC/4; j4++) {
            float4 wv = W4[j4];
            acc[j4*4+0] += xv*wv.x; acc[j4*4+1] += xv*wv.y;
            acc[j4*4+2] += xv*wv.z; acc[j4*4+3] += xv*wv.w;
        }
    }
#pragma unroll
    for (int j = 0; j < NC; j++) outp[c0 + j] = acc[j];
}

__device__ __forceinline__ void attn_row(
    const float* __restrict__ qrow, const float* __restrict__ Kt,
    const float* __restrict__ Vt, float* __restrict__ o)
{
    float qr[64];
#pragma unroll
    for (int d = 0; d < 64; d++) qr[d] = qrow[d];
    float sc[64];
    float m = -1e30f;
    for (int j = 0; j < 64; j++) {
        const float4* kr = (const float4*)(Kt + j * 64);
        float a = 0.f;
#pragma unroll
        for (int d4 = 0; d4 < 16; d4++) {
            float4 kv = kr[d4];
            a += qr[d4*4]*kv.x + qr[d4*4+1]*kv.y + qr[d4*4+2]*kv.z + qr[d4*4+3]*kv.w;
        }
        sc[j] = a * 0.125f;
        m = fmaxf(m, sc[j]);
    }
    float s = 0.f;
#pragma unroll
    for (int j = 0; j < 64; j++) { sc[j] = expf(sc[j] - m); s += sc[j]; }
    float is = 1.0f / s;
#pragma unroll
    for (int d = 0; d < 64; d++) o[d] = 0.f;
    for (int j = 0; j < 64; j++) {
        float p = sc[j] * is;
        const float4* vr = (const float4*)(Vt + j * 64);
#pragma unroll
        for (int d4 = 0; d4 < 16; d4++) {
            float4 vv = vr[d4];
            o[d4*4+0] += p*vv.x; o[d4*4+1] += p*vv.y;
            o[d4*4+2] += p*vv.z; o[d4*4+3] += p*vv.w;
        }
    }
}

__global__ __launch_bounds__(256) void attn_kernel(
    const float* __restrict__ ctx,
    const float* __restrict__ Wq, const float* __restrict__ bq,
    const float* __restrict__ Wk, const float* __restrict__ bk,
    const float* __restrict__ Wv, const float* __restrict__ bv,
    const float* __restrict__ Wcq, const float* __restrict__ bcq,
    const float* __restrict__ Wck, const float* __restrict__ bck,
    const float* __restrict__ Wcv, const float* __restrict__ bcv,
    const float* __restrict__ smix,
    const float* __restrict__ tpart, const float* __restrict__ np2,
    float* __restrict__ ot)
{
    extern __shared__ float sm[];
    float* s_tok  = sm;
    float* s_q    = sm + 4096;
    float* s_k    = sm + 2*4096;
    float* s_v    = sm + 3*4096;
    float* s_cq   = sm + 4*4096;
    float* s_ck   = sm + 5*4096;
    float* s_cv   = sm + 6*4096;
    float* s_norm = sm + 7*4096;   // 64 floats

    const int bh = blockIdx.x;
    const int b = bh >> 3, h = bh & 7;
    const int tid = threadIdx.x;

    // norm stage 2 (64 rows, 16 entries each)
    if (tid < 64) {
        float s = 0.f;
#pragma unroll
        for (int c = 0; c < 16; c++)
            s += np2[((size_t)(b * 16 + c)) * 512 + h * 64 + tid];
        s_norm[tid] = 1.0f / (s + EPS);
    }
    __syncthreads();

    // tok reduction + normalize -> s_tok
    for (int idx = tid; idx < 4096; idx += 256) {
        float s = 0.f;
#pragma unroll
        for (int c = 0; c < TOK_CHUNKS; c++)
            s += tpart[((size_t)bh * TOK_CHUNKS + c) * 4096 + idx];
        s_tok[idx] = s * s_norm[idx >> 6];
    }
    __syncthreads();

    {
        const int pid = tid >> 6;
        const int i   = tid & 63;
        const float* W; const float* bb; float* dst;
        if (pid == 0)      { W = Wq;  bb = bq;  dst = s_q;  }
        else if (pid == 1) { W = Wk;  bb = bk;  dst = s_k;  }
        else if (pid == 2) { W = Wv;  bb = bv;  dst = s_v;  }
        else               { W = Wcq; bb = bcq; dst = s_cq; }
        row_gemm_cols<64>(&s_tok[i*64], 64, W, bb, &dst[i*64], 0);
    }
    {
        const int mat = tid >> 7;
        const int sub = tid & 127;
        const int i   = sub >> 1;
        const int c0  = (sub & 1) * 32;
        const float* crow = ctx + ((size_t)bh*64 + i) * 256;
        if (mat == 0) row_gemm_cols<32>(crow, 256, Wck, bck, &s_ck[i*64], c0);
        else          row_gemm_cols<32>(crow, 256, Wcv, bcv, &s_cv[i*64], c0);
    }
    __syncthreads();

    if (tid < 64) {
        float o[64];
        attn_row(&s_q[tid*64], s_k, s_v, o);
#pragma unroll
        for (int d = 0; d < 64; d++) s_tok[tid*64 + d] = o[d];
    } else if (tid < 128) {
        const int i = tid - 64;
        float o[64];
        attn_row(&s_cq[i*64], s_ck, s_cv, o);
#pragma unroll
        for (int d = 0; d < 64; d++) s_cq[i*64 + d] = o[d];
    }
    __syncthreads();

    const float gmix = 1.0f / (1.0f + expf(-smix[0]));
    for (int idx = tid; idx < 4096; idx += 256)
        ot[(size_t)bh*4096 + idx] = gmix * s_tok[idx] + (1.0f - gmix) * s_cq[idx];
}

// ============================================================
// M^T[b][c][hg] = sum_d out_tok[b,hg,d] * Wo[h*64+d, c]  (fp16 out)
// ============================================================
__global__ __launch_bounds__(256) void m_kernel(
    const float* __restrict__ Wo, const float* __restrict__ ot,
    __half* __restrict__ MT)
{
    __shared__ float s_ot[4096];
    __shared__ float s_wo[64 * 128];
    const int bh = blockIdx.y;
    const int h = bh & 7, b = bh >> 3;
    const int c0 = blockIdx.x * 128;
    const int tid = threadIdx.x;

    for (int idx = tid; idx < 1024; idx += 256)
        ((float4*)s_ot)[idx] = ((const float4*)(ot + (size_t)bh * 4096))[idx];
    for (int idx = tid; idx < 2048; idx += 256) {
        int d = idx >> 5;
        int c4 = idx & 31;
        ((float4*)s_wo)[idx] = *(const float4*)(Wo + (size_t)(h*64 + d)*512 + c0 + c4*4);
    }
    __syncthreads();

    const int g0 = (tid >> 3) * 2;
    const int ct = (tid & 7) * 16;
    float acc[2][16];
#pragma unroll
    for (int g = 0; g < 2; g++)
#pragma unroll
        for (int c = 0; c < 16; c++) acc[g][c] = 0.f;

    for (int d = 0; d < 64; d++) {
        float a0 = s_ot[g0*64 + d];
        float a1 = s_ot[(g0+1)*64 + d];
#pragma unroll
        for (int c4 = 0; c4 < 4; c4++) {
            float4 wv = *(const float4*)&s_wo[d*128 + ct + c4*4];
            acc[0][c4*4+0]+=a0*wv.x; acc[0][c4*4+1]+=a0*wv.y; acc[0][c4*4+2]+=a0*wv.z; acc[0][c4*4+3]+=a0*wv.w;
            acc[1][c4*4+0]+=a1*wv.x; acc[1][c4*4+1]+=a1*wv.y; acc[1][c4*4+2]+=a1*wv.z; acc[1][c4*4+3]+=a1*wv.w;
        }
    }

#pragma unroll
    for (int g = 0; g < 2; g++) {
        int hg = h*64 + g0 + g;
#pragma unroll
        for (int c = 0; c < 16; c++)
            MT[(size_t)b * 262144 + (size_t)(c0 + ct + c) * 512 + hg] =
                __float2half_rn(acc[g][c]);
    }
}

// ============================================================
// host launcher
// ============================================================
extern "C" void kernel_launch(void* const* d_in, const int* in_sizes, int n_in,
                              void* d_out, int out_size)
{
    const float* x      = (const float*)d_in[0];
    const float* ctx    = (const float*)d_in[1];
    const float* Wx     = (const float*)d_in[2];
    const float* bx     = (const float*)d_in[3];
    const float* Wfx    = (const float*)d_in[4];
    const float* bfx    = (const float*)d_in[5];
    const float* Wslice = (const float*)d_in[6];
    const float* bslice = (const float*)d_in[7];
    const float* temp   = (const float*)d_in[8];
    const float* Wq     = (const float*)d_in[9];
    const float* bq     = (const float*)d_in[10];
    const float* Wk     = (const float*)d_in[11];
    const float* bk     = (const float*)d_in[12];
    const float* Wv     = (const float*)d_in[13];
    const float* bv     = (const float*)d_in[14];
    const float* Wcq    = (const float*)d_in[15];
    const float* bcq    = (const float*)d_in[16];
    const float* Wck    = (const float*)d_in[17];
    const float* bck    = (const float*)d_in[18];
    const float* Wcv    = (const float*)d_in[19];
    const float* bcv    = (const float*)d_in[20];
    const float* smix   = (const float*)d_in[21];
    const float* Wo     = (const float*)d_in[22];
    const float* bo     = (const float*)d_in[23];
    float* out = (float*)d_out;

    void *p;
    cudaGetSymbolAddress(&p, g_xh);    __half* xh    = (__half*)p;
    cudaGetSymbolAddress(&p, g_wh);    __half* wh    = (__half*)p;
    cudaGetSymbolAddress(&p, g_fxh);   __half* fxh   = (__half*)p;
    cudaGetSymbolAddress(&p, g_npart); float* npart  = (float*)p;
    cudaGetSymbolAddress(&p, g_np2);   float* np2    = (float*)p;
    cudaGetSymbolAddress(&p, g_tpart); float* tpart  = (float*)p;
    cudaGetSymbolAddress(&p, g_ot);    float* ot     = (float*)p;
    cudaGetSymbolAddress(&p, g_MTh);   __half* MTh   = (__half*)p;
    cudaGetSymbolAddress(&p, g_WcatTh);__half* WcatT = (__half*)p;
    cudaGetSymbolAddress(&p, g_bcomb); float* bcomb  = (float*)p;

    cudaFuncSetAttribute(f16_gemm<1>, cudaFuncAttributeMaxDynamicSharedMemorySize, SM_GEMM);
    cudaFuncSetAttribute(f16_gemm<0>, cudaFuncAttributeMaxDynamicSharedMemorySize, SM_GEMM);
    cudaFuncSetAttribute(tokpart_mma_kernel, cudaFuncAttributeMaxDynamicSharedMemorySize, TPT_SMEM);
    cudaFuncSetAttribute(attn_kernel, cudaFuncAttributeMaxDynamicSharedMemorySize, (7*4096+64)*4);

    // 0: fused prologue (x->fp16 | WcatT assembly | bcomb)
    prep_kernel<<<PREP_BLKS, 256>>>(x, xh, Wfx, Wx, Wslice, temp, bx, bslice, WcatT, bcomb);
    // 1: merged fp16 GEMM: softmax->wh(+npart) | bias->fxh
    f16_gemm<1><<<dim3(8, 512), 256, SM_GEMM>>>(
        xh, WcatT, bcomb, bfx, wh, fxh, nullptr, npart, CC, 0, 0);
    // 2: norm stage 1 (parallel, coalesced)
    norm_stage1_kernel<<<32, 512>>>(npart, np2);
    // 3: tokens = w^T @ fx (tensor cores)
    tokpart_mma_kernel<<<dim3(TOK_CHUNKS, 16), 256, TPT_SMEM>>>(fxh, wh, tpart);
    // 4: tiny attention (fuses tok/norm final reductions)
    attn_kernel<<<16, 256, (7*4096+64)*4>>>(ctx, Wq, bq, Wk, bk, Wv, bv,
                                            Wcq, bcq, Wck, bck, Wcv, bcv,
                                            smix, tpart, np2, ot);
    // 5: fold out_tok @ Wo -> M^T (fp16)
    m_kernel<<<dim3(4, 16), 256>>>(Wo, ot, MTh);
    // 6: out = w @ M[b] + bo (fp16 GEMM, B per-batch)
    f16_gemm<0><<<dim3(4, 512), 256, SM_GEMM>>>(
        wh, MTh, bo, nullptr, nullptr, nullptr, out, nullptr, INNER, NN, 512*512);
}

// round 15
// speedup vs baseline: 1.1237x; 1.0105x over previous
#include <cuda_runtime.h>
#include <cuda_fp16.h>
#include <math.h>
#include <stdint.h>

// ---------------- problem constants ----------------
#define BB 2
#define NN 32768
#define CC 512
#define HH 8
#define DH 64
#define GG 64
#define CD 256
#define ROWS (BB*NN)          // 65536
#define INNER (HH*DH)         // 512
#define EPS 1e-5f
#define TOK_CHUNKS 16

// ---------------- scratch ----------------
__device__ __half g_xh   [ROWS * CC];
__device__ __half g_wh   [ROWS * INNER];
__device__ __half g_fxh  [ROWS * INNER];
__device__ float  g_npart[512 * 512];
__device__ float  g_np2  [32 * 512];
__device__ float  g_tpart[16 * TOK_CHUNKS * 4096];
__device__ float  g_ot   [16 * 4096];
__device__ float  g_ckv  [2 * 16 * 4096];
__device__ __half g_MTh  [BB * 512 * 512];
__device__ __half g_WcatTh[1024 * 512];
__device__ float  g_bcomb[512];

// ---------------- helpers ----------------
__device__ __forceinline__ void cp16(void* dst, const void* src) {
    unsigned d = (unsigned)__cvta_generic_to_shared(dst);
    asm volatile("cp.async.cg.shared.global [%0], [%1], 16;" :: "r"(d), "l"(src));
}
__device__ __forceinline__ void mma_f16(float* c, const unsigned* a, const unsigned* b) {
    asm volatile(
        "mma.sync.aligned.m16n8k16.row.col.f32.f16.f16.f32 "
        "{%0,%1,%2,%3},{%4,%5,%6,%7},{%8,%9},{%0,%1,%2,%3};"
        : "+f"(c[0]), "+f"(c[1]), "+f"(c[2]), "+f"(c[3])
        : "r"(a[0]), "r"(a[1]), "r"(a[2]), "r"(a[3]), "r"(b[0]), "r"(b[1]));
}
#define LDSM4(r0, r1, r2, r3, addr) \
    asm volatile("ldmatrix.sync.aligned.m8n8.x4.shared.b16 {%0,%1,%2,%3}, [%4];" \
        : "=r"(r0), "=r"(r1), "=r"(r2), "=r"(r3) : "r"(addr))
#define LDSM4T(r0, r1, r2, r3, addr) \
    asm volatile("ldmatrix.sync.aligned.m8n8.x4.trans.shared.b16 {%0,%1,%2,%3}, [%4];" \
        : "=r"(r0), "=r"(r1), "=r"(r2), "=r"(r3) : "r"(addr))

// ============================================================
// fused prologue (block-range dispatch)
// ============================================================
#define ROUND_BLKS 2048
#define WFX_BLKS 1024
#define WCOMB_BLKS 512
#define PREP_BLKS (ROUND_BLKS + WFX_BLKS + WCOMB_BLKS)

__global__ __launch_bounds__(256) void prep_kernel(
    const float* __restrict__ x, __half* __restrict__ xh,
    const float* __restrict__ Wfx,
    const float* __restrict__ Wx, const float* __restrict__ Wslice,
    const float* __restrict__ temp,
    const float* __restrict__ bx, const float* __restrict__ bslice,
    __half* __restrict__ WcatT, float* __restrict__ bcomb)
{
    const int tid = threadIdx.x;
    const int blk = blockIdx.x;

    if (blk < ROUND_BLKS) {
        const int n4 = ROWS * CC / 4;
        int idx = blk * 256 + tid;
        const int stride = ROUND_BLKS * 256;
        for (; idx < n4; idx += stride) {
            float4 v = ((const float4*)x)[idx];
            __half2* o = (__half2*)xh + idx * 2;
            o[0] = __floats2half2_rn(v.x, v.y);
            o[1] = __floats2half2_rn(v.z, v.w);
        }
    } else if (blk < ROUND_BLKS + WFX_BLKS) {
        int idx = (blk - ROUND_BLKS) * 256 + tid;
        int k = idx >> 9;
        int n = idx & 511;
        WcatT[(size_t)(512 + n) * 512 + k] = __float2half_rn(Wfx[(size_t)k * 512 + n]);
    } else {
        __shared__ float sWs[4096];
        __shared__ float sx[512];
        __shared__ float sit[8];
        const int cr = blk - (ROUND_BLKS + WFX_BLKS);
        for (int i = tid; i < 4096; i += 256) sWs[i] = Wslice[i];
        sx[tid] = Wx[(size_t)cr * 512 + tid];
        sx[tid + 256] = Wx[(size_t)cr * 512 + tid + 256];
        if (tid < 8) {
            float tv = temp[tid];
            sit[tid] = 1.0f / fminf(fmaxf(tv, 0.1f), 5.0f);
        }
        __syncthreads();
#pragma unroll
        for (int rep = 0; rep < 2; rep++) {
            const int o = tid + rep * 256;
            const int h = o >> 6, gg = o & 63;
            float acc = 0.f;
#pragma unroll 8
            for (int d = 0; d < 64; d++)
                acc += sx[h*64 + d] * sWs[d*64 + gg];
            WcatT[(size_t)o * 512 + cr] = __float2half_rn(acc * sit[h]);
            if (cr == 0) {
                float acc2 = bslice[gg];
                for (int d = 0; d < 64; d++)
                    acc2 += bx[h*64 + d] * sWs[d*64 + gg];
                bcomb[o] = acc2 * sit[h];
            }
        }
    }
}

// ============================================================
// ck/cv projections: ckv[mat][bh][row][64] = ctx[bh] @ Wc{k,v} + b
// 64 blocks (mat*32 + bh*2 + rowhalf), 256 threads, NC=8.
// Column order within each row matches reference (sequential c).
// ============================================================
__global__ __launch_bounds__(256) void ckcv_kernel(
    const float* __restrict__ ctx,
    const float* __restrict__ Wck, const float* __restrict__ bck,
    const float* __restrict__ Wcv, const float* __restrict__ bcv,
    float* __restrict__ ckv)
{
    const int blk = blockIdx.x;
    const int mat = blk >> 5;
    const int bh  = (blk >> 1) & 15;
    const int rh  = blk & 1;
    const int tid = threadIdx.x;
    const int i   = rh * 32 + (tid >> 3);
    const int c0  = (tid & 7) * 8;
    const float* W  = mat ? Wcv : Wck;
    const float* bb = mat ? bcv : bck;
    const float* crow = ctx + ((size_t)bh * 64 + i) * 256;

    float acc[8];
#pragma unroll
    for (int j = 0; j < 8; j++) acc[j] = bb[c0 + j];
    for (int d = 0; d < 256; d++) {
        float xv = crow[d];
        const float4* W4 = (const float4*)(W + (size_t)d * 64 + c0);
#pragma unroll
        for (int j4 = 0; j4 < 2; j4++) {
            float4 wv = W4[j4];
            acc[j4*4+0] += xv*wv.x; acc[j4*4+1] += xv*wv.y;
            acc[j4*4+2] += xv*wv.z; acc[j4*4+3] += xv*wv.w;
        }
    }
    float* o = ckv + ((size_t)(mat * 16 + bh) * 64 + i) * 64 + c0;
#pragma unroll
    for (int j4 = 0; j4 < 2; j4++)
        *(float4*)(o + j4*4) = make_float4(acc[j4*4], acc[j4*4+1], acc[j4*4+2], acc[j4*4+3]);
}

// ============================================================
// FP16 GEMM 128x128x32, 8 warps (warp tile 32x64), 4-stage cp.async,
// ldmatrix fragment loads, register-resident softmax epilogue.
// ============================================================
#define AH 40
#define STG_BYTES 10240
#define SM_GEMM (8 * STG_BYTES)

template<int MODE>
__global__ __launch_bounds__(256, 2) void f16_gemm(
    const __half* __restrict__ A, const __half* __restrict__ BT,
    const float* __restrict__ biasA, const float* __restrict__ biasB,
    __half* __restrict__ wOut, __half* __restrict__ fxOut,
    float* __restrict__ outF, float* __restrict__ npart,
    int K, int bRowsPerBatch, int bMatStride)
{
    extern __shared__ char smem[];

    const int tid  = threadIdx.x;
    const int lane = tid & 31;
    const int warp = tid >> 5;
    const int wr   = warp >> 1;
    const int wc   = warp & 1;
    const int row0 = blockIdx.y * 128;
    const int col0 = blockIdx.x * 128;

    const __half* Bp = BT;
    if (bRowsPerBatch) Bp += (size_t)(row0 / bRowsPerBatch) * (size_t)bMatStride;

    float c[2][8][4];
#pragma unroll
    for (int i = 0; i < 2; i++)
#pragma unroll
        for (int j = 0; j < 8; j++)
#pragma unroll
            for (int r = 0; r < 4; r++) c[i][j][r] = 0.f;

    const int g = lane >> 2;
    const int t = lane & 3;

    const uint32_t As0 = (uint32_t)__cvta_generic_to_shared(smem);
    const uint32_t Bs0 = As0 + 4 * STG_BYTES;
    uint32_t aOff[2], bOff[4];
#pragma unroll
    for (int i = 0; i < 2; i++)
        aOff[i] = (uint32_t)(((wr*32 + i*16 + (lane & 15)) * AH + ((lane >> 4) << 3)) * 2);
#pragma unroll
    for (int jp = 0; jp < 4; jp++)
        bOff[jp] = (uint32_t)(((wc*64 + jp*16 + ((lane >> 4) << 3) + (lane & 7)) * AH
                               + (((lane >> 3) & 1) << 3)) * 2);

    const int sr  = tid >> 2;
    const int skc = (tid & 3) * 8;

    auto stage = [&](int kt, int buf) {
        __half* a = (__half*)(smem + buf * STG_BYTES);
        __half* b = (__half*)(smem + 4 * STG_BYTES + buf * STG_BYTES);
        const int k0 = kt << 5;
#pragma unroll
        for (int it = 0; it < 2; it++) {
            int r = sr + it * 64;
            cp16(&a[r * AH + skc], A  + (size_t)(row0 + r) * K + k0 + skc);
            cp16(&b[r * AH + skc], Bp + (size_t)(col0 + r) * K + k0 + skc);
        }
    };

    const int ntiles = K >> 5;
    stage(0, 0); asm volatile("cp.async.commit_group;");
    stage(1, 1); asm volatile("cp.async.commit_group;");
    stage(2, 2); asm volatile("cp.async.commit_group;");

    for (int kt = 0; kt < ntiles; kt++) {
        asm volatile("cp.async.wait_group 2;");
        __syncthreads();
        if (kt + 3 < ntiles) stage(kt + 3, (kt + 3) & 3);
        asm volatile("cp.async.commit_group;");

        const uint32_t aBuf = As0 + (kt & 3) * STG_BYTES;
        const uint32_t bBuf = Bs0 + (kt & 3) * STG_BYTES;
#pragma unroll
        for (int ks = 0; ks < 2; ks++) {
            const uint32_t kbB = ks * 32;
            unsigned a[2][4], b[8][2];
#pragma unroll
            for (int i = 0; i < 2; i++)
                LDSM4(a[i][0], a[i][1], a[i][2], a[i][3], aBuf + aOff[i] + kbB);
#pragma unroll
            for (int jp = 0; jp < 4; jp++)
                LDSM4(b[jp*2][0], b[jp*2][1], b[jp*2+1][0], b[jp*2+1][1],
                      bBuf + bOff[jp] + kbB);
#pragma unroll
            for (int i = 0; i < 2; i++)
#pragma unroll
                for (int j = 0; j < 8; j++)
                    mma_f16(c[i][j], a[i], b[j]);
        }
        __syncthreads();
    }

    if (MODE == 1 && col0 < 512) {
        const int colbase = col0 + wc * 64;
        float bv[16];
#pragma unroll
        for (int j = 0; j < 8; j++) {
            bv[j*2]   = biasA[colbase + j*8 + t*2];
            bv[j*2+1] = biasA[colbase + j*8 + t*2 + 1];
        }
#pragma unroll
        for (int i = 0; i < 2; i++)
#pragma unroll
            for (int j = 0; j < 8; j++) {
                c[i][j][0] += bv[j*2];   c[i][j][1] += bv[j*2+1];
                c[i][j][2] += bv[j*2];   c[i][j][3] += bv[j*2+1];
            }

        float cs[16];
#pragma unroll
        for (int m = 0; m < 16; m++) cs[m] = 0.f;

#pragma unroll
        for (int i = 0; i < 2; i++)
#pragma unroll
            for (int h2 = 0; h2 < 2; h2++) {
                float mx = -1e30f;
#pragma unroll
                for (int j = 0; j < 8; j++)
                    mx = fmaxf(mx, fmaxf(c[i][j][h2*2], c[i][j][h2*2+1]));
                mx = fmaxf(mx, __shfl_xor_sync(0xffffffffu, mx, 1));
                mx = fmaxf(mx, __shfl_xor_sync(0xffffffffu, mx, 2));
                float s = 0.f;
#pragma unroll
                for (int j = 0; j < 8; j++) {
                    float e0 = __expf(c[i][j][h2*2]   - mx);
                    float e1 = __expf(c[i][j][h2*2+1] - mx);
                    c[i][j][h2*2] = e0; c[i][j][h2*2+1] = e1;
                    s += e0 + e1;
                }
                s += __shfl_xor_sync(0xffffffffu, s, 1);
                s += __shfl_xor_sync(0xffffffffu, s, 2);
                const float is = 1.0f / s;
                const size_t row = (size_t)(row0 + wr*32 + i*16 + h2*8 + g);
#pragma unroll
                for (int j = 0; j < 8; j++) {
                    __half2 h = __floats2half2_rn(c[i][j][h2*2]*is, c[i][j][h2*2+1]*is);
                    *(__half2*)(wOut + row * 512 + colbase + j*8 + t*2) = h;
                    float2 f = __half22float2(h);
                    cs[j*2] += f.x; cs[j*2+1] += f.y;
                }
            }

#pragma unroll
        for (int m = 0; m < 16; m++) {
            cs[m] += __shfl_xor_sync(0xffffffffu, cs[m], 4);
            cs[m] += __shfl_xor_sync(0xffffffffu, cs[m], 8);
            cs[m] += __shfl_xor_sync(0xffffffffu, cs[m], 16);
        }
        float* npsum = (float*)smem;
        if (lane < 4) {
#pragma unroll
            for (int j = 0; j < 8; j++) {
                npsum[wr*128 + wc*64 + j*8 + lane*2]     = cs[j*2];
                npsum[wr*128 + wc*64 + j*8 + lane*2 + 1] = cs[j*2+1];
            }
        }
        __syncthreads();
        if (tid < 128)
            npart[(size_t)blockIdx.y * 512 + col0 + tid] =
                npsum[tid] + npsum[128+tid] + npsum[256+tid] + npsum[384+tid];
    } else if (MODE == 1) {
        const int cg = col0 - 512 + wc * 64;
#pragma unroll
        for (int i = 0; i < 2; i++) {
            int rm = row0 + wr*32 + i*16 + g;
#pragma unroll
            for (int j = 0; j < 8; j++) {
                int cn = cg + j*8 + t*2;
                float b0 = biasB[cn], b1 = biasB[cn + 1];
                *(__half2*)(fxOut + (size_t)rm * 512 + cn) =
                    __floats2half2_rn(c[i][j][0] + b0, c[i][j][1] + b1);
                *(__half2*)(fxOut + (size_t)(rm + 8) * 512 + cn) =
                    __floats2half2_rn(c[i][j][2] + b0, c[i][j][3] + b1);
            }
        }
    } else {
        const int cg = col0 + wc * 64;
#pragma unroll
        for (int i = 0; i < 2; i++) {
            int rm = row0 + wr*32 + i*16 + g;
#pragma unroll
            for (int j = 0; j < 8; j++) {
                int cn = cg + j*8 + t*2;
                float b0 = biasA[cn], b1 = biasA[cn + 1];
                *(float2*)(outF + (size_t)rm * 512 + cn) =
                    make_float2(c[i][j][0] + b0, c[i][j][1] + b1);
                *(float2*)(outF + (size_t)(rm + 8) * 512 + cn) =
                    make_float2(c[i][j][2] + b0, c[i][j][3] + b1);
            }
        }
    }
}

// ============================================================
// tokens partials via tensor cores + norm stage 1 (block-range)
// grid (TOK_CHUNKS+2, 16): x<16 -> tokpart chunk; x>=16 -> norm blocks
// ============================================================
#define WT 72
#define TPT_TILE_H (128 * WT)
#define TPT_SMEM (4 * TPT_TILE_H * 2)

__global__ __launch_bounds__(256) void tokpart_mma_kernel(
    const __half* __restrict__ fx, const __half* __restrict__ w,
    float* __restrict__ part,
    const float* __restrict__ npart, float* __restrict__ np2)
{
    extern __shared__ char smem[];
    const int tid  = threadIdx.x;

    if (blockIdx.x >= TOK_CHUNKS) {
        // norm stage 1: 32 blocks, each sums 16 row-blocks over 512 cols
        const int nb = (blockIdx.x - TOK_CHUNKS) * 16 + blockIdx.y;  // 0..31
        const int b = nb >> 4, rbg = nb & 15;
#pragma unroll
        for (int rep = 0; rep < 2; rep++) {
            const int hg = tid + rep * 256;
            float s = 0.f;
#pragma unroll
            for (int rb = 0; rb < 16; rb++)
                s += npart[((size_t)(b * 256 + rbg * 16 + rb)) * 512 + hg];
            np2[(size_t)nb * 512 + hg] = s;
        }
        return;
    }

    const int chunk = blockIdx.x;
    const int bh = blockIdx.y;
    const int b = bh >> 3, h = bh & 7;
    const size_t rbase = (size_t)b * NN + (size_t)chunk * 2048;

    const int lane = tid & 31;
    const int warp = tid >> 5;
    const int wm   = warp >> 1;
    const int wn   = warp & 1;

    const uint32_t S0 = (uint32_t)__cvta_generic_to_shared(smem);

    float c[4][4];
#pragma unroll
    for (int nj = 0; nj < 4; nj++)
#pragma unroll
        for (int r = 0; r < 4; r++) c[nj][r] = 0.f;

    const uint32_t aOff = (uint32_t)(((((lane >> 4) << 3) + (lane & 7)) * WT
                           + wm*16 + (((lane >> 3) & 1) << 3)) * 2);
    uint32_t bOff[2];
#pragma unroll
    for (int p2 = 0; p2 < 2; p2++)
        bOff[p2] = (uint32_t)((((((lane >> 3) & 1) << 3) + (lane & 7)) * WT
                    + wn*32 + p2*16 + ((lane >> 4) << 3)) * 2);

    auto stage = [&](int kt, int buf) {
        __half* wsb = (__half*)smem + buf * TPT_TILE_H;
        __half* fsb = (__half*)smem + 2 * TPT_TILE_H + buf * TPT_TILE_H;
#pragma unroll
        for (int it = 0; it < 4; it++) {
            int s = tid + it * 256;
            int r = s >> 3;
            int c8 = (s & 7) * 8;
            size_t row = rbase + (size_t)kt * 128 + r;
            cp16(&wsb[r * WT + c8], w  + row * 512 + h * 64 + c8);
            cp16(&fsb[r * WT + c8], fx + row * 512 + h * 64 + c8);
        }
    };

    stage(0, 0);
    asm volatile("cp.async.commit_group;");

    for (int kt = 0; kt < 16; kt++) {
        asm volatile("cp.async.wait_group 0;");
        __syncthreads();
        if (kt + 1 < 16) {
            stage(kt + 1, (kt + 1) & 1);
            asm volatile("cp.async.commit_group;");
        }
        const int buf = kt & 1;
        const uint32_t wBuf = S0 + buf * TPT_TILE_H * 2;
        const uint32_t fBuf = S0 + (2 + buf) * TPT_TILE_H * 2;
#pragma unroll
        for (int ks = 0; ks < 8; ks++) {
            const uint32_t ksB = (uint32_t)(ks * 16 * WT * 2);
            unsigned a[4], bb[4][2];
            LDSM4T(a[0], a[1], a[2], a[3], wBuf + aOff + ksB);
            LDSM4T(bb[0][0], bb[0][1], bb[1][0], bb[1][1], fBuf + bOff[0] + ksB);
            LDSM4T(bb[2][0], bb[2][1], bb[3][0], bb[3][1], fBuf + bOff[1] + ksB);
#pragma unroll
            for (int nj = 0; nj < 4; nj++)
                mma_f16(c[nj], a, bb[nj]);
        }
        __syncthreads();
    }

    const int g4 = lane >> 2;
    const int t  = lane & 3;
    float* p = part + ((size_t)bh * TOK_CHUNKS + chunk) * 4096;
#pragma unroll
    for (int nj = 0; nj < 4; nj++) {
        int col = wn*32 + nj*8 + t*2;
        *(float2*)&p[(wm*16 + g4) * 64 + col]     = make_float2(c[nj][0], c[nj][1]);
        *(float2*)&p[(wm*16 + g4 + 8) * 64 + col] = make_float2(c[nj][2], c[nj][3]);
    }
}

// ============================================================
// tiny attention — fuses tok/norm final reductions; ck/cv precomputed
// ============================================================
template<int NC>
__device__ __forceinline__ void row_gemm_cols(
    const float* __restrict__ xrow, int Kd,
    const float* __restrict__ W, const float* __restrict__ bias,
    float* __restrict__ outp, int c0)
{
    float acc[NC];
#pragma unroll
    for (int j = 0; j < NC; j++) acc[j] = bias[c0 + j];
    for (int d = 0; d < Kd; d++) {
        float xv = xrow[d];
        const float4* W4 = (const float4*)(W + (size_t)d * 64 + c0);
#pragma unroll
        for (int j4 = 0; j4 < NC/4; j4++) {
            float4 wv = W4[j4];
            acc[j4*4+0] += xv*wv.x; acc[j4*4+1] += xv*wv.y;
            acc[j4*4+2] += xv*wv.z; acc[j4*4+3] += xv*wv.w;
        }
    }
#pragma unroll
    for (int j = 0; j < NC; j++) outp[c0 + j] = acc[j];
}

__device__ __forceinline__ void attn_row(
    const float* __restrict__ qrow, const float* __restrict__ Kt,
    const float* __restrict__ Vt, float* __restrict__ o)
{
    float qr[64];
#pragma unroll
    for (int d = 0; d < 64; d++) qr[d] = qrow[d];
    float sc[64];
    float m = -1e30f;
    for (int j = 0; j < 64; j++) {
        const float4* kr = (const float4*)(Kt + j * 64);
        float a = 0.f;
#pragma unroll
        for (int d4 = 0; d4 < 16; d4++) {
            float4 kv = kr[d4];
            a += qr[d4*4]*kv.x + qr[d4*4+1]*kv.y + qr[d4*4+2]*kv.z + qr[d4*4+3]*kv.w;
        }
        sc[j] = a * 0.125f;
        m = fmaxf(m, sc[j]);
    }
    float s = 0.f;
#pragma unroll
    for (int j = 0; j < 64; j++) { sc[j] = expf(sc[j] - m); s += sc[j]; }
    float is = 1.0f / s;
#pragma unroll
    for (int d = 0; d < 64; d++) o[d] = 0.f;
    for (int j = 0; j < 64; j++) {
        float p = sc[j] * is;
        const float4* vr = (const float4*)(Vt + j * 64);
#pragma unroll
        for (int d4 = 0; d4 < 16; d4++) {
            float4 vv = vr[d4];
            o[d4*4+0] += p*vv.x; o[d4*4+1] += p*vv.y;
            o[d4*4+2] += p*vv.z; o[d4*4+3] += p*vv.w;
        }
    }
}

__global__ __launch_bounds__(256) void attn_kernel(
    const float* __restrict__ ckv,
    const float* __restrict__ Wq, const float* __restrict__ bq,
    const float* __restrict__ Wk, const float* __restrict__ bk,
    const float* __restrict__ Wv, const float* __restrict__ bv,
    const float* __restrict__ Wcq, const float* __restrict__ bcq,
    const float* __restrict__ smix,
    const float* __restrict__ tpart, const float* __restrict__ np2,
    float* __restrict__ ot)
{
    extern __shared__ float sm[];
    float* s_tok  = sm;
    float* s_q    = sm + 4096;
    float* s_k    = sm + 2*4096;
    float* s_v    = sm + 3*4096;
    float* s_cq   = sm + 4*4096;
    float* s_ck   = sm + 5*4096;
    float* s_cv   = sm + 6*4096;
    float* s_norm = sm + 7*4096;

    const int bh = blockIdx.x;
    const int b = bh >> 3, h = bh & 7;
    const int tid = threadIdx.x;

    if (tid < 64) {
        float s = 0.f;
#pragma unroll
        for (int c = 0; c < 16; c++)
            s += np2[((size_t)(b * 16 + c)) * 512 + h * 64 + tid];
        s_norm[tid] = 1.0f / (s + EPS);
    }
    __syncthreads();

    for (int idx = tid; idx < 4096; idx += 256) {
        float s = 0.f;
#pragma unroll
        for (int c = 0; c < TOK_CHUNKS; c++)
            s += tpart[((size_t)bh * TOK_CHUNKS + c) * 4096 + idx];
        s_tok[idx] = s * s_norm[idx >> 6];
        s_ck[idx] = ckv[(size_t)bh * 4096 + idx];
        s_cv[idx] = ckv[(size_t)(16 + bh) * 4096 + idx];
    }
    __syncthreads();

    {
        const int pid = tid >> 6;
        const int i   = tid & 63;
        const float* W; const float* bb; float* dst;
        if (pid == 0)      { W = Wq;  bb = bq;  dst = s_q;  }
        else if (pid == 1) { W = Wk;  bb = bk;  dst = s_k;  }
        else if (pid == 2) { W = Wv;  bb = bv;  dst = s_v;  }
        else               { W = Wcq; bb = bcq; dst = s_cq; }
        row_gemm_cols<64>(&s_tok[i*64], 64, W, bb, &dst[i*64], 0);
    }
    __syncthreads();

    if (tid < 64) {
        float o[64];
        attn_row(&s_q[tid*64], s_k, s_v, o);
#pragma unroll
        for (int d = 0; d < 64; d++) s_tok[tid*64 + d] = o[d];
    } else if (tid < 128) {
        const int i = tid - 64;
        float o[64];
        attn_row(&s_cq[i*64], s_ck, s_cv, o);
#pragma unroll
        for (int d = 0; d < 64; d++) s_cq[i*64 + d] = o[d];
    }
    __syncthreads();

    const float gmix = 1.0f / (1.0f + expf(-smix[0]));
    for (int idx = tid; idx < 4096; idx += 256)
        ot[(size_t)bh*4096 + idx] = gmix * s_tok[idx] + (1.0f - gmix) * s_cq[idx];
}

// ============================================================
// M^T[b][c][hg] = sum_d out_tok[b,hg,d] * Wo[h*64+d, c]  (fp16 out)
// ============================================================
__global__ __launch_bounds__(256) void m_kernel(
    const float* __restrict__ Wo, const float* __restrict__ ot,
    __half* __restrict__ MT)
{
    __shared__ float s_ot[4096];
    __shared__ float s_wo[64 * 128];
    const int bh = blockIdx.y;
    const int h = bh & 7, b = bh >> 3;
    const int c0 = blockIdx.x * 128;
    const int tid = threadIdx.x;

    for (int idx = tid; idx < 1024; idx += 256)
        ((float4*)s_ot)[idx] = ((const float4*)(ot + (size_t)bh * 4096))[idx];
    for (int idx = tid; idx < 2048; idx += 256) {
        int d = idx >> 5;
        int c4 = idx & 31;
        ((float4*)s_wo)[idx] = *(const float4*)(Wo + (size_t)(h*64 + d)*512 + c0 + c4*4);
    }
    __syncthreads();

    const int g0 = (tid >> 3) * 2;
    const int ct = (tid & 7) * 16;
    float acc[2][16];
#pragma unroll
    for (int g = 0; g < 2; g++)
#pragma unroll
        for (int c = 0; c < 16; c++) acc[g][c] = 0.f;

    for (int d = 0; d < 64; d++) {
        float a0 = s_ot[g0*64 + d];
        float a1 = s_ot[(g0+1)*64 + d];
#pragma unroll
        for (int c4 = 0; c4 < 4; c4++) {
            float4 wv = *(const float4*)&s_wo[d*128 + ct + c4*4];
            acc[0][c4*4+0]+=a0*wv.x; acc[0][c4*4+1]+=a0*wv.y; acc[0][c4*4+2]+=a0*wv.z; acc[0][c4*4+3]+=a0*wv.w;
            acc[1][c4*4+0]+=a1*wv.x; acc[1][c4*4+1]+=a1*wv.y; acc[1][c4*4+2]+=a1*wv.z; acc[1][c4*4+3]+=a1*wv.w;
        }
    }

#pragma unroll
    for (int g = 0; g < 2; g++) {
        int hg = h*64 + g0 + g;
#pragma unroll
        for (int c = 0; c < 16; c++)
            MT[(size_t)b * 262144 + (size_t)(c0 + ct + c) * 512 + hg] =
                __float2half_rn(acc[g][c]);
    }
}

// ============================================================
// host launcher
// ============================================================
extern "C" void kernel_launch(void* const* d_in, const int* in_sizes, int n_in,
                              void* d_out, int out_size)
{
    const float* x      = (const float*)d_in[0];
    const float* ctx    = (const float*)d_in[1];
    const float* Wx     = (const float*)d_in[2];
    const float* bx     = (const float*)d_in[3];
    const float* Wfx    = (const float*)d_in[4];
    const float* bfx    = (const float*)d_in[5];
    const float* Wslice = (const float*)d_in[6];
    const float* bslice = (const float*)d_in[7];
    const float* temp   = (const float*)d_in[8];
    const float* Wq     = (const float*)d_in[9];
    const float* bq     = (const float*)d_in[10];
    const float* Wk     = (const float*)d_in[11];
    const float* bk     = (const float*)d_in[12];
    const float* Wv     = (const float*)d_in[13];
    const float* bv     = (const float*)d_in[14];
    const float* Wcq    = (const float*)d_in[15];
    const float* bcq    = (const float*)d_in[16];
    const float* Wck    = (const float*)d_in[17];
    const float* bck    = (const float*)d_in[18];
    const float* Wcv    = (const float*)d_in[19];
    const float* bcv    = (const float*)d_in[20];
    const float* smix   = (const float*)d_in[21];
    const float* Wo     = (const float*)d_in[22];
    const float* bo     = (const float*)d_in[23];
    float* out = (float*)d_out;

    void *p;
    cudaGetSymbolAddress(&p, g_xh);    __half* xh    = (__half*)p;
    cudaGetSymbolAddress(&p, g_wh);    __half* wh    = (__half*)p;
    cudaGetSymbolAddress(&p, g_fxh);   __half* fxh   = (__half*)p;
    cudaGetSymbolAddress(&p, g_npart); float* npart  = (float*)p;
    cudaGetSymbolAddress(&p, g_np2);   float* np2    = (float*)p;
    cudaGetSymbolAddress(&p, g_tpart); float* tpart  = (float*)p;
    cudaGetSymbolAddress(&p, g_ot);    float* ot     = (float*)p;
    cudaGetSymbolAddress(&p, g_ckv);   float* ckv    = (float*)p;
    cudaGetSymbolAddress(&p, g_MTh);   __half* MTh   = (__half*)p;
    cudaGetSymbolAddress(&p, g_WcatTh);__half* WcatT = (__half*)p;
    cudaGetSymbolAddress(&p, g_bcomb); float* bcomb  = (float*)p;

    cudaFuncSetAttribute(f16_gemm<1>, cudaFuncAttributeMaxDynamicSharedMemorySize, SM_GEMM);
    cudaFuncSetAttribute(f16_gemm<0>, cudaFuncAttributeMaxDynamicSharedMemorySize, SM_GEMM);
    cudaFuncSetAttribute(tokpart_mma_kernel, cudaFuncAttributeMaxDynamicSharedMemorySize, TPT_SMEM);
    cudaFuncSetAttribute(attn_kernel, cudaFuncAttributeMaxDynamicSharedMemorySize, (7*4096+64)*4);

    // 0: fused prologue (x->fp16 | WcatT assembly | bcomb)
    prep_kernel<<<PREP_BLKS, 256>>>(x, xh, Wfx, Wx, Wslice, temp, bx, bslice, WcatT, bcomb);
    // 0b: ck/cv projections (independent, cheap, runs while GEMM queued behind)
    ckcv_kernel<<<64, 256>>>(ctx, Wck, bck, Wcv, bcv, ckv);
    // 1: merged fp16 GEMM: softmax->wh(+npart) | bias->fxh
    f16_gemm<1><<<dim3(8, 512), 256, SM_GEMM>>>(
        xh, WcatT, bcomb, bfx, wh, fxh, nullptr, npart, CC, 0, 0);
    // 2: tokens = w^T @ fx (tensor cores) + norm stage 1 (fused grid)
    tokpart_mma_kernel<<<dim3(TOK_CHUNKS + 2, 16), 256, TPT_SMEM>>>(
        fxh, wh, tpart, npart, np2);
    // 3: tiny attention (fuses tok/norm final reductions)
    attn_kernel<<<16, 256, (7*4096+64)*4>>>(ckv, Wq, bq, Wk, bk, Wv, bv,
                                            Wcq, bcq, smix, tpart, np2, ot);
    // 4: fold out_tok @ Wo -> M^T (fp16)
    m_kernel<<<dim3(4, 16), 256>>>(Wo, ot, MTh);
    // 5: out = w @ M[b] + bo (fp16 GEMM, B per-batch)
    f16_gemm<0><<<dim3(4, 512), 256, SM_GEMM>>>(
        wh, MTh, bo, nullptr, nullptr, nullptr, out, nullptr, INNER, NN, 512*512);
}

// round 16
// speedup vs baseline: 1.1754x; 1.0460x over previous
#include <cuda_runtime.h>
#include <cuda_fp16.h>
#include <math.h>
#include <stdint.h>

// ---------------- problem constants ----------------
#define BB 2
#define NN 32768
#define CC 512
#define HH 8
#define DH 64
#define GG 64
#define CD 256
#define ROWS (BB*NN)          // 65536
#define INNER (HH*DH)         // 512
#define EPS 1e-5f
#define TOK_CHUNKS 16

// ---------------- scratch ----------------
__device__ __half g_xh   [ROWS * CC];
__device__ __half g_wh   [ROWS * INNER];
__device__ __half g_fxh  [ROWS * INNER];
__device__ float  g_npart[512 * 512];
__device__ float  g_np2  [32 * 512];
__device__ float  g_tpart[16 * TOK_CHUNKS * 4096];
__device__ float  g_ot   [16 * 4096];
__device__ float  g_ckv  [2 * 16 * 4096];
__device__ __half g_MTh  [BB * 512 * 512];
__device__ __half g_WcatTh[1024 * 512];
__device__ float  g_bcomb[512];

// ---------------- helpers ----------------
__device__ __forceinline__ void cp16(void* dst, const void* src) {
    unsigned d = (unsigned)__cvta_generic_to_shared(dst);
    asm volatile("cp.async.cg.shared.global [%0], [%1], 16;" :: "r"(d), "l"(src));
}
__device__ __forceinline__ void mma_f16(float* c, const unsigned* a, const unsigned* b) {
    asm volatile(
        "mma.sync.aligned.m16n8k16.row.col.f32.f16.f16.f32 "
        "{%0,%1,%2,%3},{%4,%5,%6,%7},{%8,%9},{%0,%1,%2,%3};"
        : "+f"(c[0]), "+f"(c[1]), "+f"(c[2]), "+f"(c[3])
        : "r"(a[0]), "r"(a[1]), "r"(a[2]), "r"(a[3]), "r"(b[0]), "r"(b[1]));
}
#define LDSM4(r0, r1, r2, r3, addr) \
    asm volatile("ldmatrix.sync.aligned.m8n8.x4.shared.b16 {%0,%1,%2,%3}, [%4];" \
        : "=r"(r0), "=r"(r1), "=r"(r2), "=r"(r3) : "r"(addr))
#define LDSM4T(r0, r1, r2, r3, addr) \
    asm volatile("ldmatrix.sync.aligned.m8n8.x4.trans.shared.b16 {%0,%1,%2,%3}, [%4];" \
        : "=r"(r0), "=r"(r1), "=r"(r2), "=r"(r3) : "r"(addr))

// ============================================================
// fused prologue (block-range dispatch)
// ============================================================
#define ROUND_BLKS 2048
#define WFX_BLKS 1024
#define WCOMB_BLKS 512
#define PREP_BLKS (ROUND_BLKS + WFX_BLKS + WCOMB_BLKS)

__global__ __launch_bounds__(256) void prep_kernel(
    const float* __restrict__ x, __half* __restrict__ xh,
    const float* __restrict__ Wfx,
    const float* __restrict__ Wx, const float* __restrict__ Wslice,
    const float* __restrict__ temp,
    const float* __restrict__ bx, const float* __restrict__ bslice,
    __half* __restrict__ WcatT, float* __restrict__ bcomb)
{
    const int tid = threadIdx.x;
    const int blk = blockIdx.x;

    if (blk < ROUND_BLKS) {
        const int n4 = ROWS * CC / 4;
        int idx = blk * 256 + tid;
        const int stride = ROUND_BLKS * 256;
        for (; idx < n4; idx += stride) {
            float4 v = ((const float4*)x)[idx];
            __half2* o = (__half2*)xh + idx * 2;
            o[0] = __floats2half2_rn(v.x, v.y);
            o[1] = __floats2half2_rn(v.z, v.w);
        }
    } else if (blk < ROUND_BLKS + WFX_BLKS) {
        int idx = (blk - ROUND_BLKS) * 256 + tid;
        int k = idx >> 9;
        int n = idx & 511;
        WcatT[(size_t)(512 + n) * 512 + k] = __float2half_rn(Wfx[(size_t)k * 512 + n]);
    } else {
        __shared__ float sWs[4096];
        __shared__ float sx[512];
        __shared__ float sit[8];
        const int cr = blk - (ROUND_BLKS + WFX_BLKS);
        for (int i = tid; i < 4096; i += 256) sWs[i] = Wslice[i];
        sx[tid] = Wx[(size_t)cr * 512 + tid];
        sx[tid + 256] = Wx[(size_t)cr * 512 + tid + 256];
        if (tid < 8) {
            float tv = temp[tid];
            sit[tid] = 1.0f / fminf(fmaxf(tv, 0.1f), 5.0f);
        }
        __syncthreads();
#pragma unroll
        for (int rep = 0; rep < 2; rep++) {
            const int o = tid + rep * 256;
            const int h = o >> 6, gg = o & 63;
            float acc = 0.f;
#pragma unroll 8
            for (int d = 0; d < 64; d++)
                acc += sx[h*64 + d] * sWs[d*64 + gg];
            WcatT[(size_t)o * 512 + cr] = __float2half_rn(acc * sit[h]);
            if (cr == 0) {
                float acc2 = bslice[gg];
                for (int d = 0; d < 64; d++)
                    acc2 += bx[h*64 + d] * sWs[d*64 + gg];
                bcomb[o] = acc2 * sit[h];
            }
        }
    }
}

// ============================================================
// ck/cv projections
// ============================================================
__global__ __launch_bounds__(256) void ckcv_kernel(
    const float* __restrict__ ctx,
    const float* __restrict__ Wck, const float* __restrict__ bck,
    const float* __restrict__ Wcv, const float* __restrict__ bcv,
    float* __restrict__ ckv)
{
    const int blk = blockIdx.x;
    const int mat = blk >> 5;
    const int bh  = (blk >> 1) & 15;
    const int rh  = blk & 1;
    const int tid = threadIdx.x;
    const int i   = rh * 32 + (tid >> 3);
    const int c0  = (tid & 7) * 8;
    const float* W  = mat ? Wcv : Wck;
    const float* bb = mat ? bcv : bck;
    const float* crow = ctx + ((size_t)bh * 64 + i) * 256;

    float acc[8];
#pragma unroll
    for (int j = 0; j < 8; j++) acc[j] = bb[c0 + j];
    for (int d = 0; d < 256; d++) {
        float xv = crow[d];
        const float4* W4 = (const float4*)(W + (size_t)d * 64 + c0);
#pragma unroll
        for (int j4 = 0; j4 < 2; j4++) {
            float4 wv = W4[j4];
            acc[j4*4+0] += xv*wv.x; acc[j4*4+1] += xv*wv.y;
            acc[j4*4+2] += xv*wv.z; acc[j4*4+3] += xv*wv.w;
        }
    }
    float* o = ckv + ((size_t)(mat * 16 + bh) * 64 + i) * 64 + c0;
#pragma unroll
    for (int j4 = 0; j4 < 2; j4++)
        *(float4*)(o + j4*4) = make_float4(acc[j4*4], acc[j4*4+1], acc[j4*4+2], acc[j4*4+3]);
}

// ============================================================
// FP16 GEMM 128x128x64, 8 warps (warp tile 32x64), 3-stage cp.async,
// ldmatrix fragment loads, register-resident softmax epilogue.
// ============================================================
#define AH 72                       // padded k-stride (halves), 144B rows
#define MAT_BYTES (128 * AH * 2)    // 18432
#define STAGE_BYTES (2 * MAT_BYTES) // 36864 (A + B)
#define SM_GEMM (3 * STAGE_BYTES)   // 110592

template<int MODE>
__global__ __launch_bounds__(256, 2) void f16_gemm(
    const __half* __restrict__ A, const __half* __restrict__ BT,
    const float* __restrict__ biasA, const float* __restrict__ biasB,
    __half* __restrict__ wOut, __half* __restrict__ fxOut,
    float* __restrict__ outF, float* __restrict__ npart,
    int K, int bRowsPerBatch, int bMatStride)
{
    extern __shared__ char smem[];

    const int tid  = threadIdx.x;
    const int lane = tid & 31;
    const int warp = tid >> 5;
    const int wr   = warp >> 1;
    const int wc   = warp & 1;
    const int row0 = blockIdx.y * 128;
    const int col0 = blockIdx.x * 128;

    const __half* Bp = BT;
    if (bRowsPerBatch) Bp += (size_t)(row0 / bRowsPerBatch) * (size_t)bMatStride;

    float c[2][8][4];
#pragma unroll
    for (int i = 0; i < 2; i++)
#pragma unroll
        for (int j = 0; j < 8; j++)
#pragma unroll
            for (int r = 0; r < 4; r++) c[i][j][r] = 0.f;

    const int g = lane >> 2;
    const int t = lane & 3;

    const uint32_t S0 = (uint32_t)__cvta_generic_to_shared(smem);
    uint32_t aOff[2], bOff[4];
#pragma unroll
    for (int i = 0; i < 2; i++)
        aOff[i] = (uint32_t)(((wr*32 + i*16 + (lane & 15)) * AH + ((lane >> 4) << 3)) * 2);
#pragma unroll
    for (int jp = 0; jp < 4; jp++)
        bOff[jp] = (uint32_t)(((wc*64 + jp*16 + ((lane >> 4) << 3) + (lane & 7)) * AH
                               + (((lane >> 3) & 1) << 3)) * 2);

    auto stage = [&](int kt, int buf) {
        __half* a = (__half*)(smem + buf * STAGE_BYTES);
        __half* b = (__half*)(smem + buf * STAGE_BYTES + MAT_BYTES);
        const int k0 = kt << 6;
#pragma unroll
        for (int it = 0; it < 4; it++) {
            int s = tid + it * 256;            // 0..1023
            int r = s >> 3;                    // 0..127
            int c8 = (s & 7) * 8;              // half offset
            cp16(&a[r * AH + c8], A  + (size_t)(row0 + r) * K + k0 + c8);
            cp16(&b[r * AH + c8], Bp + (size_t)(col0 + r) * K + k0 + c8);
        }
    };

    const int ntiles = K >> 6;   // 8 for K=512
    stage(0, 0); asm volatile("cp.async.commit_group;");
    stage(1, 1); asm volatile("cp.async.commit_group;");

    for (int kt = 0; kt < ntiles; kt++) {
        asm volatile("cp.async.wait_group 1;");
        __syncthreads();
        if (kt + 2 < ntiles) stage(kt + 2, (kt + 2) % 3);
        asm volatile("cp.async.commit_group;");

        const uint32_t aBuf = S0 + (kt % 3) * STAGE_BYTES;
        const uint32_t bBuf = aBuf + MAT_BYTES;
#pragma unroll
        for (int ks = 0; ks < 4; ks++) {
            const uint32_t kbB = ks * 32;
            unsigned a[2][4], b[8][2];
#pragma unroll
            for (int i = 0; i < 2; i++)
                LDSM4(a[i][0], a[i][1], a[i][2], a[i][3], aBuf + aOff[i] + kbB);
#pragma unroll
            for (int jp = 0; jp < 4; jp++)
                LDSM4(b[jp*2][0], b[jp*2][1], b[jp*2+1][0], b[jp*2+1][1],
                      bBuf + bOff[jp] + kbB);
#pragma unroll
            for (int i = 0; i < 2; i++)
#pragma unroll
                for (int j = 0; j < 8; j++)
                    mma_f16(c[i][j], a[i], b[j]);
        }
        __syncthreads();
    }

    if (MODE == 1 && col0 < 512) {
        const int colbase = col0 + wc * 64;
        float bv[16];
#pragma unroll
        for (int j = 0; j < 8; j++) {
            bv[j*2]   = biasA[colbase + j*8 + t*2];
            bv[j*2+1] = biasA[colbase + j*8 + t*2 + 1];
        }
#pragma unroll
        for (int i = 0; i < 2; i++)
#pragma unroll
            for (int j = 0; j < 8; j++) {
                c[i][j][0] += bv[j*2];   c[i][j][1] += bv[j*2+1];
                c[i][j][2] += bv[j*2];   c[i][j][3] += bv[j*2+1];
            }

        float cs[16];
#pragma unroll
        for (int m = 0; m < 16; m++) cs[m] = 0.f;

#pragma unroll
        for (int i = 0; i < 2; i++)
#pragma unroll
            for (int h2 = 0; h2 < 2; h2++) {
                float mx = -1e30f;
#pragma unroll
                for (int j = 0; j < 8; j++)
                    mx = fmaxf(mx, fmaxf(c[i][j][h2*2], c[i][j][h2*2+1]));
                mx = fmaxf(mx, __shfl_xor_sync(0xffffffffu, mx, 1));
                mx = fmaxf(mx, __shfl_xor_sync(0xffffffffu, mx, 2));
                float s = 0.f;
#pragma unroll
                for (int j = 0; j < 8; j++) {
                    float e0 = __expf(c[i][j][h2*2]   - mx);
                    float e1 = __expf(c[i][j][h2*2+1] - mx);
                    c[i][j][h2*2] = e0; c[i][j][h2*2+1] = e1;
                    s += e0 + e1;
                }
                s += __shfl_xor_sync(0xffffffffu, s, 1);
                s += __shfl_xor_sync(0xffffffffu, s, 2);
                const float is = 1.0f / s;
                const size_t row = (size_t)(row0 + wr*32 + i*16 + h2*8 + g);
#pragma unroll
                for (int j = 0; j < 8; j++) {
                    __half2 h = __floats2half2_rn(c[i][j][h2*2]*is, c[i][j][h2*2+1]*is);
                    *(__half2*)(wOut + row * 512 + colbase + j*8 + t*2) = h;
                    float2 f = __half22float2(h);
                    cs[j*2] += f.x; cs[j*2+1] += f.y;
                }
            }

#pragma unroll
        for (int m = 0; m < 16; m++) {
            cs[m] += __shfl_xor_sync(0xffffffffu, cs[m], 4);
            cs[m] += __shfl_xor_sync(0xffffffffu, cs[m], 8);
            cs[m] += __shfl_xor_sync(0xffffffffu, cs[m], 16);
        }
        float* npsum = (float*)smem;
        if (lane < 4) {
#pragma unroll
            for (int j = 0; j < 8; j++) {
                npsum[wr*128 + wc*64 + j*8 + lane*2]     = cs[j*2];
                npsum[wr*128 + wc*64 + j*8 + lane*2 + 1] = cs[j*2+1];
            }
        }
        __syncthreads();
        if (tid < 128)
            npart[(size_t)blockIdx.y * 512 + col0 + tid] =
                npsum[tid] + npsum[128+tid] + npsum[256+tid] + npsum[384+tid];
    } else if (MODE == 1) {
        const int cg = col0 - 512 + wc * 64;
#pragma unroll
        for (int i = 0; i < 2; i++) {
            int rm = row0 + wr*32 + i*16 + g;
#pragma unroll
            for (int j = 0; j < 8; j++) {
                int cn = cg + j*8 + t*2;
                float b0 = biasB[cn], b1 = biasB[cn + 1];
                *(__half2*)(fxOut + (size_t)rm * 512 + cn) =
                    __floats2half2_rn(c[i][j][0] + b0, c[i][j][1] + b1);
                *(__half2*)(fxOut + (size_t)(rm + 8) * 512 + cn) =
                    __floats2half2_rn(c[i][j][2] + b0, c[i][j][3] + b1);
            }
        }
    } else {
        const int cg = col0 + wc * 64;
#pragma unroll
        for (int i = 0; i < 2; i++) {
            int rm = row0 + wr*32 + i*16 + g;
#pragma unroll
            for (int j = 0; j < 8; j++) {
                int cn = cg + j*8 + t*2;
                float b0 = biasA[cn], b1 = biasA[cn + 1];
                *(float2*)(outF + (size_t)rm * 512 + cn) =
                    make_float2(c[i][j][0] + b0, c[i][j][1] + b1);
                *(float2*)(outF + (size_t)(rm + 8) * 512 + cn) =
                    make_float2(c[i][j][2] + b0, c[i][j][3] + b1);
            }
        }
    }
}

// ============================================================
// tokens partials via tensor cores + norm stage 1 (block-range)
// ============================================================
#define WT 72
#define TPT_TILE_H (128 * WT)
#define TPT_SMEM (4 * TPT_TILE_H * 2)

__global__ __launch_bounds__(256) void tokpart_mma_kernel(
    const __half* __restrict__ fx, const __half* __restrict__ w,
    float* __restrict__ part,
    const float* __restrict__ npart, float* __restrict__ np2)
{
    extern __shared__ char smem[];
    const int tid  = threadIdx.x;

    if (blockIdx.x >= TOK_CHUNKS) {
        const int nb = (blockIdx.x - TOK_CHUNKS) * 16 + blockIdx.y;
        const int b = nb >> 4, rbg = nb & 15;
#pragma unroll
        for (int rep = 0; rep < 2; rep++) {
            const int hg = tid + rep * 256;
            float s = 0.f;
#pragma unroll
            for (int rb = 0; rb < 16; rb++)
                s += npart[((size_t)(b * 256 + rbg * 16 + rb)) * 512 + hg];
            np2[(size_t)nb * 512 + hg] = s;
        }
        return;
    }

    const int chunk = blockIdx.x;
    const int bh = blockIdx.y;
    const int b = bh >> 3, h = bh & 7;
    const size_t rbase = (size_t)b * NN + (size_t)chunk * 2048;

    const int lane = tid & 31;
    const int warp = tid >> 5;
    const int wm   = warp >> 1;
    const int wn   = warp & 1;

    const uint32_t S0 = (uint32_t)__cvta_generic_to_shared(smem);

    float c[4][4];
#pragma unroll
    for (int nj = 0; nj < 4; nj++)
#pragma unroll
        for (int r = 0; r < 4; r++) c[nj][r] = 0.f;

    const uint32_t aOff = (uint32_t)(((((lane >> 4) << 3) + (lane & 7)) * WT
                           + wm*16 + (((lane >> 3) & 1) << 3)) * 2);
    uint32_t bOff[2];
#pragma unroll
    for (int p2 = 0; p2 < 2; p2++)
        bOff[p2] = (uint32_t)((((((lane >> 3) & 1) << 3) + (lane & 7)) * WT
                    + wn*32 + p2*16 + ((lane >> 4) << 3)) * 2);

    auto stage = [&](int kt, int buf) {
        __half* wsb = (__half*)smem + buf * TPT_TILE_H;
        __half* fsb = (__half*)smem + 2 * TPT_TILE_H + buf * TPT_TILE_H;
#pragma unroll
        for (int it = 0; it < 4; it++) {
            int s = tid + it * 256;
            int r = s >> 3;
            int c8 = (s & 7) * 8;
            size_t row = rbase + (size_t)kt * 128 + r;
            cp16(&wsb[r * WT + c8], w  + row * 512 + h * 64 + c8);
            cp16(&fsb[r * WT + c8], fx + row * 512 + h * 64 + c8);
        }
    };

    stage(0, 0);
    asm volatile("cp.async.commit_group;");

    for (int kt = 0; kt < 16; kt++) {
        asm volatile("cp.async.wait_group 0;");
        __syncthreads();
        if (kt + 1 < 16) {
            stage(kt + 1, (kt + 1) & 1);
            asm volatile("cp.async.commit_group;");
        }
        const int buf = kt & 1;
        const uint32_t wBuf = S0 + buf * TPT_TILE_H * 2;
        const uint32_t fBuf = S0 + (2 + buf) * TPT_TILE_H * 2;
#pragma unroll
        for (int ks = 0; ks < 8; ks++) {
            const uint32_t ksB = (uint32_t)(ks * 16 * WT * 2);
            unsigned a[4], bb[4][2];
            LDSM4T(a[0], a[1], a[2], a[3], wBuf + aOff + ksB);
            LDSM4T(bb[0][0], bb[0][1], bb[1][0], bb[1][1], fBuf + bOff[0] + ksB);
            LDSM4T(bb[2][0], bb[2][1], bb[3][0], bb[3][1], fBuf + bOff[1] + ksB);
#pragma unroll
            for (int nj = 0; nj < 4; nj++)
                mma_f16(c[nj], a, bb[nj]);
        }
        __syncthreads();
    }

    const int g4 = lane >> 2;
    const int t  = lane & 3;
    float* p = part + ((size_t)bh * TOK_CHUNKS + chunk) * 4096;
#pragma unroll
    for (int nj = 0; nj < 4; nj++) {
        int col = wn*32 + nj*8 + t*2;
        *(float2*)&p[(wm*16 + g4) * 64 + col]     = make_float2(c[nj][0], c[nj][1]);
        *(float2*)&p[(wm*16 + g4 + 8) * 64 + col] = make_float2(c[nj][2], c[nj][3]);
    }
}

// ============================================================
// tiny attention — fuses tok/norm final reductions; ck/cv precomputed
// ============================================================
template<int NC>
__device__ __forceinline__ void row_gemm_cols(
    const float* __restrict__ xrow, int Kd,
    const float* __restrict__ W, const float* __restrict__ bias,
    float* __restrict__ outp, int c0)
{
    float acc[NC];
#pragma unroll
    for (int j = 0; j < NC; j++) acc[j] = bias[c0 + j];
    for (int d = 0; d < Kd; d++) {
        float xv = xrow[d];
        const float4* W4 = (const float4*)(W + (size_t)d * 64 + c0);
#pragma unroll
        for (int j4 = 0; j4 < NC/4; j4++) {
            float4 wv = W4[j4];
            acc[j4*4+0] += xv*wv.x; acc[j4*4+1] += xv*wv.y;
            acc[j4*4+2] += xv*wv.z; acc[j4*4+3] += xv*wv.w;
        }
    }
#pragma unroll
    for (int j = 0; j < NC; j++) outp[c0 + j] = acc[j];
}

__device__ __forceinline__ void attn_row(
    const float* __restrict__ qrow, const float* __restrict__ Kt,
    const float* __restrict__ Vt, float* __restrict__ o)
{
    float qr[64];
#pragma unroll
    for (int d = 0; d < 64; d++) qr[d] = qrow[d];
    float sc[64];
    float m = -1e30f;
    for (int j = 0; j < 64; j++) {
        const float4* kr = (const float4*)(Kt + j * 64);
        float a = 0.f;
#pragma unroll
        for (int d4 = 0; d4 < 16; d4++) {
            float4 kv = kr[d4];
            a += qr[d4*4]*kv.x + qr[d4*4+1]*kv.y + qr[d4*4+2]*kv.z + qr[d4*4+3]*kv.w;
        }
        sc[j] = a * 0.125f;
        m = fmaxf(m, sc[j]);
    }
    float s = 0.f;
#pragma unroll
    for (int j = 0; j < 64; j++) { sc[j] = expf(sc[j] - m); s += sc[j]; }
    float is = 1.0f / s;
#pragma unroll
    for (int d = 0; d < 64; d++) o[d] = 0.f;
    for (int j = 0; j < 64; j++) {
        float p = sc[j] * is;
        const float4* vr = (const float4*)(Vt + j * 64);
#pragma unroll
        for (int d4 = 0; d4 < 16; d4++) {
            float4 vv = vr[d4];
            o[d4*4+0] += p*vv.x; o[d4*4+1] += p*vv.y;
            o[d4*4+2] += p*vv.z; o[d4*4+3] += p*vv.w;
        }
    }
}

__global__ __launch_bounds__(256) void attn_kernel(
    const float* __restrict__ ckv,
    const float* __restrict__ Wq, const float* __restrict__ bq,
    const float* __restrict__ Wk, const float* __restrict__ bk,
    const float* __restrict__ Wv, const float* __restrict__ bv,
    const float* __restrict__ Wcq, const float* __restrict__ bcq,
    const float* __restrict__ smix,
    const float* __restrict__ tpart, const float* __restrict__ np2,
    float* __restrict__ ot)
{
    extern __shared__ float sm[];
    float* s_tok  = sm;
    float* s_q    = sm + 4096;
    float* s_k    = sm + 2*4096;
    float* s_v    = sm + 3*4096;
    float* s_cq   = sm + 4*4096;
    float* s_ck   = sm + 5*4096;
    float* s_cv   = sm + 6*4096;
    float* s_norm = sm + 7*4096;

    const int bh = blockIdx.x;
    const int b = bh >> 3, h = bh & 7;
    const int tid = threadIdx.x;

    if (tid < 64) {
        float s = 0.f;
#pragma unroll
        for (int c = 0; c < 16; c++)
            s += np2[((size_t)(b * 16 + c)) * 512 + h * 64 + tid];
        s_norm[tid] = 1.0f / (s + EPS);
    }
    __syncthreads();

    for (int idx = tid; idx < 4096; idx += 256) {
        float s = 0.f;
#pragma unroll
        for (int c = 0; c < TOK_CHUNKS; c++)
            s += tpart[((size_t)bh * TOK_CHUNKS + c) * 4096 + idx];
        s_tok[idx] = s * s_norm[idx >> 6];
        s_ck[idx] = ckv[(size_t)bh * 4096 + idx];
        s_cv[idx] = ckv[(size_t)(16 + bh) * 4096 + idx];
    }
    __syncthreads();

    {
        const int pid = tid >> 6;
        const int i   = tid & 63;
        const float* W; const float* bb; float* dst;
        if (pid == 0)      { W = Wq;  bb = bq;  dst = s_q;  }
        else if (pid == 1) { W = Wk;  bb = bk;  dst = s_k;  }
        else if (pid == 2) { W = Wv;  bb = bv;  dst = s_v;  }
        else               { W = Wcq; bb = bcq; dst = s_cq; }
        row_gemm_cols<64>(&s_tok[i*64], 64, W, bb, &dst[i*64], 0);
    }
    __syncthreads();

    if (tid < 64) {
        float o[64];
        attn_row(&s_q[tid*64], s_k, s_v, o);
#pragma unroll
        for (int d = 0; d < 64; d++) s_tok[tid*64 + d] = o[d];
    } else if (tid < 128) {
        const int i = tid - 64;
        float o[64];
        attn_row(&s_cq[i*64], s_ck, s_cv, o);
#pragma unroll
        for (int d = 0; d < 64; d++) s_cq[i*64 + d] = o[d];
    }
    __syncthreads();

    const float gmix = 1.0f / (1.0f + expf(-smix[0]));
    for (int idx = tid; idx < 4096; idx += 256)
        ot[(size_t)bh*4096 + idx] = gmix * s_tok[idx] + (1.0f - gmix) * s_cq[idx];
}

// ============================================================
// M^T[b][c][hg] = sum_d out_tok[b,hg,d] * Wo[h*64+d, c]  (fp16 out)
// ============================================================
__global__ __launch_bounds__(256) void m_kernel(
    const float* __restrict__ Wo, const float* __restrict__ ot,
    __half* __restrict__ MT)
{
    __shared__ float s_ot[4096];
    __shared__ float s_wo[64 * 128];
    const int bh = blockIdx.y;
    const int h = bh & 7, b = bh >> 3;
    const int c0 = blockIdx.x * 128;
    const int tid = threadIdx.x;

    for (int idx = tid; idx < 1024; idx += 256)
        ((float4*)s_ot)[idx] = ((const float4*)(ot + (size_t)bh * 4096))[idx];
    for (int idx = tid; idx < 2048; idx += 256) {
        int d = idx >> 5;
        int c4 = idx & 31;
        ((float4*)s_wo)[idx] = *(const float4*)(Wo + (size_t)(h*64 + d)*512 + c0 + c4*4);
    }
    __syncthreads();

    const int g0 = (tid >> 3) * 2;
    const int ct = (tid & 7) * 16;
    float acc[2][16];
#pragma unroll
    for (int g = 0; g < 2; g++)
#pragma unroll
        for (int c = 0; c < 16; c++) acc[g][c] = 0.f;

    for (int d = 0; d < 64; d++) {
        float a0 = s_ot[g0*64 + d];
        float a1 = s_ot[(g0+1)*64 + d];
#pragma unroll
        for (int c4 = 0; c4 < 4; c4++) {
            float4 wv = *(const float4*)&s_wo[d*128 + ct + c4*4];
            acc[0][c4*4+0]+=a0*wv.x; acc[0][c4*4+1]+=a0*wv.y; acc[0][c4*4+2]+=a0*wv.z; acc[0][c4*4+3]+=a0*wv.w;
            acc[1][c4*4+0]+=a1*wv.x; acc[1][c4*4+1]+=a1*wv.y; acc[1][c4*4+2]+=a1*wv.z; acc[1][c4*4+3]+=a1*wv.w;
        }
    }

#pragma unroll
    for (int g = 0; g < 2; g++) {
        int hg = h*64 + g0 + g;
#pragma unroll
        for (int c = 0; c < 16; c++)
            MT[(size_t)b * 262144 + (size_t)(c0 + ct + c) * 512 + hg] =
                __float2half_rn(acc[g][c]);
    }
}

// ============================================================
// host launcher
// ============================================================
extern "C" void kernel_launch(void* const* d_in, const int* in_sizes, int n_in,
                              void* d_out, int out_size)
{
    const float* x      = (const float*)d_in[0];
    const float* ctx    = (const float*)d_in[1];
    const float* Wx     = (const float*)d_in[2];
    const float* bx     = (const float*)d_in[3];
    const float* Wfx    = (const float*)d_in[4];
    const float* bfx    = (const float*)d_in[5];
    const float* Wslice = (const float*)d_in[6];
    const float* bslice = (const float*)d_in[7];
    const float* temp   = (const float*)d_in[8];
    const float* Wq     = (const float*)d_in[9];
    const float* bq     = (const float*)d_in[10];
    const float* Wk     = (const float*)d_in[11];
    const float* bk     = (const float*)d_in[12];
    const float* Wv     = (const float*)d_in[13];
    const float* bv     = (const float*)d_in[14];
    const float* Wcq    = (const float*)d_in[15];
    const float* bcq    = (const float*)d_in[16];
    const float* Wck    = (const float*)d_in[17];
    const float* bck    = (const float*)d_in[18];
    const float* Wcv    = (const float*)d_in[19];
    const float* bcv    = (const float*)d_in[20];
    const float* smix   = (const float*)d_in[21];
    const float* Wo     = (const float*)d_in[22];
    const float* bo     = (const float*)d_in[23];
    float* out = (float*)d_out;

    void *p;
    cudaGetSymbolAddress(&p, g_xh);    __half* xh    = (__half*)p;
    cudaGetSymbolAddress(&p, g_wh);    __half* wh    = (__half*)p;
    cudaGetSymbolAddress(&p, g_fxh);   __half* fxh   = (__half*)p;
    cudaGetSymbolAddress(&p, g_npart); float* npart  = (float*)p;
    cudaGetSymbolAddress(&p, g_np2);   float* np2    = (float*)p;
    cudaGetSymbolAddress(&p, g_tpart); float* tpart  = (float*)p;
    cudaGetSymbolAddress(&p, g_ot);    float* ot     = (float*)p;
    cudaGetSymbolAddress(&p, g_ckv);   float* ckv    = (float*)p;
    cudaGetSymbolAddress(&p, g_MTh);   __half* MTh   = (__half*)p;
    cudaGetSymbolAddress(&p, g_WcatTh);__half* WcatT = (__half*)p;
    cudaGetSymbolAddress(&p, g_bcomb); float* bcomb  = (float*)p;

    cudaFuncSetAttribute(f16_gemm<1>, cudaFuncAttributeMaxDynamicSharedMemorySize, SM_GEMM);
    cudaFuncSetAttribute(f16_gemm<0>, cudaFuncAttributeMaxDynamicSharedMemorySize, SM_GEMM);
    cudaFuncSetAttribute(tokpart_mma_kernel, cudaFuncAttributeMaxDynamicSharedMemorySize, TPT_SMEM);
    cudaFuncSetAttribute(attn_kernel, cudaFuncAttributeMaxDynamicSharedMemorySize, (7*4096+64)*4);

    // 0: fused prologue (x->fp16 | WcatT assembly | bcomb)
    prep_kernel<<<PREP_BLKS, 256>>>(x, xh, Wfx, Wx, Wslice, temp, bx, bslice, WcatT, bcomb);
    // 0b: ck/cv projections
    ckcv_kernel<<<64, 256>>>(ctx, Wck, bck, Wcv, bcv, ckv);
    // 1: merged fp16 GEMM: softmax->wh(+npart) | bias->fxh
    f16_gemm<1><<<dim3(8, 512), 256, SM_GEMM>>>(
        xh, WcatT, bcomb, bfx, wh, fxh, nullptr, npart, CC, 0, 0);
    // 2: tokens = w^T @ fx (tensor cores) + norm stage 1 (fused grid)
    tokpart_mma_kernel<<<dim3(TOK_CHUNKS + 2, 16), 256, TPT_SMEM>>>(
        fxh, wh, tpart, npart, np2);
    // 3: tiny attention (fuses tok/norm final reductions)
    attn_kernel<<<16, 256, (7*4096+64)*4>>>(ckv, Wq, bq, Wk, bk, Wv, bv,
                                            Wcq, bcq, smix, tpart, np2, ot);
    // 4: fold out_tok @ Wo -> M^T (fp16)
    m_kernel<<<dim3(4, 16), 256>>>(Wo, ot, MTh);
    // 5: out = w @ M[b] + bo (fp16 GEMM, B per-batch)
    f16_gemm<0><<<dim3(4, 512), 256, SM_GEMM>>>(
        wh, MTh, bo, nullptr, nullptr, nullptr, out, nullptr, INNER, NN, 512*512);
}

// round 17
// speedup vs baseline: 1.1790x; 1.0031x over previous
#include <cuda_runtime.h>
#include <cuda_fp16.h>
#include <math.h>
#include <stdint.h>

// ---------------- problem constants ----------------
#define BB 2
#define NN 32768
#define CC 512
#define HH 8
#define DH 64
#define GG 64
#define CD 256
#define ROWS (BB*NN)          // 65536
#define INNER (HH*DH)         // 512
#define EPS 1e-5f
#define TOK_CHUNKS 16

// ---------------- scratch ----------------
__device__ __half g_xh   [ROWS * CC];
__device__ __half g_wh   [ROWS * INNER];
__device__ __half g_fxh  [ROWS * INNER];
__device__ float  g_npart[512 * 512];
__device__ float  g_np2  [32 * 512];
__device__ float  g_tpart[16 * TOK_CHUNKS * 4096];
__device__ float  g_ot   [16 * 4096];
__device__ float  g_ckv  [2 * 16 * 4096];
__device__ __half g_MTh  [BB * 512 * 512];
__device__ __half g_WcatTh[1024 * 512];
__device__ float  g_bcomb[512];

// ---------------- helpers ----------------
__device__ __forceinline__ void cp16(void* dst, const void* src) {
    unsigned d = (unsigned)__cvta_generic_to_shared(dst);
    asm volatile("cp.async.cg.shared.global [%0], [%1], 16;" :: "r"(d), "l"(src));
}
__device__ __forceinline__ void mma_f16(float* c, const unsigned* a, const unsigned* b) {
    asm volatile(
        "mma.sync.aligned.m16n8k16.row.col.f32.f16.f16.f32 "
        "{%0,%1,%2,%3},{%4,%5,%6,%7},{%8,%9},{%0,%1,%2,%3};"
        : "+f"(c[0]), "+f"(c[1]), "+f"(c[2]), "+f"(c[3])
        : "r"(a[0]), "r"(a[1]), "r"(a[2]), "r"(a[3]), "r"(b[0]), "r"(b[1]));
}
#define LDSM4(r0, r1, r2, r3, addr) \
    asm volatile("ldmatrix.sync.aligned.m8n8.x4.shared.b16 {%0,%1,%2,%3}, [%4];" \
        : "=r"(r0), "=r"(r1), "=r"(r2), "=r"(r3) : "r"(addr))
#define LDSM4T(r0, r1, r2, r3, addr) \
    asm volatile("ldmatrix.sync.aligned.m8n8.x4.trans.shared.b16 {%0,%1,%2,%3}, [%4];" \
        : "=r"(r0), "=r"(r1), "=r"(r2), "=r"(r3) : "r"(addr))

// ============================================================
// fused prologue (block-range dispatch)
//   [0, 2048):      x fp32 -> xh fp16
//   [2048, 3072):   Wfx -> WcatT rows 512..1023
//   [3072, 3584):   Wcomb -> WcatT rows 0..511 (+bcomb in block 3072)
//   [3584, 3648):   ck/cv projections
// ============================================================
#define ROUND_BLKS 2048
#define WFX_BLKS 1024
#define WCOMB_BLKS 512
#define CKCV_BLKS 64
#define PREP_BLKS (ROUND_BLKS + WFX_BLKS + WCOMB_BLKS + CKCV_BLKS)

__global__ __launch_bounds__(256) void prep_kernel(
    const float* __restrict__ x, __half* __restrict__ xh,
    const float* __restrict__ Wfx,
    const float* __restrict__ Wx, const float* __restrict__ Wslice,
    const float* __restrict__ temp,
    const float* __restrict__ bx, const float* __restrict__ bslice,
    __half* __restrict__ WcatT, float* __restrict__ bcomb,
    const float* __restrict__ ctx,
    const float* __restrict__ Wck, const float* __restrict__ bck,
    const float* __restrict__ Wcv, const float* __restrict__ bcv,
    float* __restrict__ ckv)
{
    const int tid = threadIdx.x;
    const int blk = blockIdx.x;

    if (blk < ROUND_BLKS) {
        const int n4 = ROWS * CC / 4;
        int idx = blk * 256 + tid;
        const int stride = ROUND_BLKS * 256;
        for (; idx < n4; idx += stride) {
            float4 v = ((const float4*)x)[idx];
            __half2* o = (__half2*)xh + idx * 2;
            o[0] = __floats2half2_rn(v.x, v.y);
            o[1] = __floats2half2_rn(v.z, v.w);
        }
    } else if (blk < ROUND_BLKS + WFX_BLKS) {
        int idx = (blk - ROUND_BLKS) * 256 + tid;
        int k = idx >> 9;
        int n = idx & 511;
        WcatT[(size_t)(512 + n) * 512 + k] = __float2half_rn(Wfx[(size_t)k * 512 + n]);
    } else if (blk < ROUND_BLKS + WFX_BLKS + WCOMB_BLKS) {
        __shared__ float sWs[4096];
        __shared__ float sx[512];
        __shared__ float sit[8];
        const int cr = blk - (ROUND_BLKS + WFX_BLKS);
        for (int i = tid; i < 4096; i += 256) sWs[i] = Wslice[i];
        sx[tid] = Wx[(size_t)cr * 512 + tid];
        sx[tid + 256] = Wx[(size_t)cr * 512 + tid + 256];
        if (tid < 8) {
            float tv = temp[tid];
            sit[tid] = 1.0f / fminf(fmaxf(tv, 0.1f), 5.0f);
        }
        __syncthreads();
#pragma unroll
        for (int rep = 0; rep < 2; rep++) {
            const int o = tid + rep * 256;
            const int h = o >> 6, gg = o & 63;
            float acc = 0.f;
#pragma unroll 8
            for (int d = 0; d < 64; d++)
                acc += sx[h*64 + d] * sWs[d*64 + gg];
            WcatT[(size_t)o * 512 + cr] = __float2half_rn(acc * sit[h]);
            if (cr == 0) {
                float acc2 = bslice[gg];
                for (int d = 0; d < 64; d++)
                    acc2 += bx[h*64 + d] * sWs[d*64 + gg];
                bcomb[o] = acc2 * sit[h];
            }
        }
    } else {
        const int cblk = blk - (ROUND_BLKS + WFX_BLKS + WCOMB_BLKS);  // 0..63
        const int mat = cblk >> 5;
        const int bh  = (cblk >> 1) & 15;
        const int rh  = cblk & 1;
        const int i   = rh * 32 + (tid >> 3);
        const int c0  = (tid & 7) * 8;
        const float* W  = mat ? Wcv : Wck;
        const float* bb = mat ? bcv : bck;
        const float* crow = ctx + ((size_t)bh * 64 + i) * 256;

        float acc[8];
#pragma unroll
        for (int j = 0; j < 8; j++) acc[j] = bb[c0 + j];
        for (int d = 0; d < 256; d++) {
            float xv = crow[d];
            const float4* W4 = (const float4*)(W + (size_t)d * 64 + c0);
#pragma unroll
            for (int j4 = 0; j4 < 2; j4++) {
                float4 wv = W4[j4];
                acc[j4*4+0] += xv*wv.x; acc[j4*4+1] += xv*wv.y;
                acc[j4*4+2] += xv*wv.z; acc[j4*4+3] += xv*wv.w;
            }
        }
        float* o = ckv + ((size_t)(mat * 16 + bh) * 64 + i) * 64 + c0;
#pragma unroll
        for (int j4 = 0; j4 < 2; j4++)
            *(float4*)(o + j4*4) = make_float4(acc[j4*4], acc[j4*4+1], acc[j4*4+2], acc[j4*4+3]);
    }
}

// ============================================================
// FP16 GEMM 128x128x64, 8 warps (warp tile 32x64), 3-stage cp.async,
// ldmatrix fragment loads, register-resident softmax epilogue.
// ============================================================
#define AH 72
#define MAT_BYTES (128 * AH * 2)
#define STAGE_BYTES (2 * MAT_BYTES)
#define SM_GEMM (3 * STAGE_BYTES)

template<int MODE>
__global__ __launch_bounds__(256, 2) void f16_gemm(
    const __half* __restrict__ A, const __half* __restrict__ BT,
    const float* __restrict__ biasA, const float* __restrict__ biasB,
    __half* __restrict__ wOut, __half* __restrict__ fxOut,
    float* __restrict__ outF, float* __restrict__ npart,
    int K, int bRowsPerBatch, int bMatStride)
{
    extern __shared__ char smem[];

    const int tid  = threadIdx.x;
    const int lane = tid & 31;
    const int warp = tid >> 5;
    const int wr   = warp >> 1;
    const int wc   = warp & 1;
    const int row0 = blockIdx.y * 128;
    const int col0 = blockIdx.x * 128;

    const __half* Bp = BT;
    if (bRowsPerBatch) Bp += (size_t)(row0 / bRowsPerBatch) * (size_t)bMatStride;

    float c[2][8][4];
#pragma unroll
    for (int i = 0; i < 2; i++)
#pragma unroll
        for (int j = 0; j < 8; j++)
#pragma unroll
            for (int r = 0; r < 4; r++) c[i][j][r] = 0.f;

    const int g = lane >> 2;
    const int t = lane & 3;

    const uint32_t S0 = (uint32_t)__cvta_generic_to_shared(smem);
    uint32_t aOff[2], bOff[4];
#pragma unroll
    for (int i = 0; i < 2; i++)
        aOff[i] = (uint32_t)(((wr*32 + i*16 + (lane & 15)) * AH + ((lane >> 4) << 3)) * 2);
#pragma unroll
    for (int jp = 0; jp < 4; jp++)
        bOff[jp] = (uint32_t)(((wc*64 + jp*16 + ((lane >> 4) << 3) + (lane & 7)) * AH
                               + (((lane >> 3) & 1) << 3)) * 2);

    auto stage = [&](int kt, int buf) {
        __half* a = (__half*)(smem + buf * STAGE_BYTES);
        __half* b = (__half*)(smem + buf * STAGE_BYTES + MAT_BYTES);
        const int k0 = kt << 6;
#pragma unroll
        for (int it = 0; it < 4; it++) {
            int s = tid + it * 256;
            int r = s >> 3;
            int c8 = (s & 7) * 8;
            cp16(&a[r * AH + c8], A  + (size_t)(row0 + r) * K + k0 + c8);
            cp16(&b[r * AH + c8], Bp + (size_t)(col0 + r) * K + k0 + c8);
        }
    };

    const int ntiles = K >> 6;
    stage(0, 0); asm volatile("cp.async.commit_group;");
    stage(1, 1); asm volatile("cp.async.commit_group;");

    for (int kt = 0; kt < ntiles; kt++) {
        asm volatile("cp.async.wait_group 1;");
        __syncthreads();
        if (kt + 2 < ntiles) stage(kt + 2, (kt + 2) % 3);
        asm volatile("cp.async.commit_group;");

        const uint32_t aBuf = S0 + (kt % 3) * STAGE_BYTES;
        const uint32_t bBuf = aBuf + MAT_BYTES;
#pragma unroll
        for (int ks = 0; ks < 4; ks++) {
            const uint32_t kbB = ks * 32;
            unsigned a[2][4], b[8][2];
#pragma unroll
            for (int i = 0; i < 2; i++)
                LDSM4(a[i][0], a[i][1], a[i][2], a[i][3], aBuf + aOff[i] + kbB);
#pragma unroll
            for (int jp = 0; jp < 4; jp++)
                LDSM4(b[jp*2][0], b[jp*2][1], b[jp*2+1][0], b[jp*2+1][1],
                      bBuf + bOff[jp] + kbB);
#pragma unroll
            for (int i = 0; i < 2; i++)
#pragma unroll
                for (int j = 0; j < 8; j++)
                    mma_f16(c[i][j], a[i], b[j]);
        }
        __syncthreads();
    }

    if (MODE == 1 && col0 < 512) {
        const int colbase = col0 + wc * 64;
        float bv[16];
#pragma unroll
        for (int j = 0; j < 8; j++) {
            bv[j*2]   = biasA[colbase + j*8 + t*2];
            bv[j*2+1] = biasA[colbase + j*8 + t*2 + 1];
        }
#pragma unroll
        for (int i = 0; i < 2; i++)
#pragma unroll
            for (int j = 0; j < 8; j++) {
                c[i][j][0] += bv[j*2];   c[i][j][1] += bv[j*2+1];
                c[i][j][2] += bv[j*2];   c[i][j][3] += bv[j*2+1];
            }

        float cs[16];
#pragma unroll
        for (int m = 0; m < 16; m++) cs[m] = 0.f;

#pragma unroll
        for (int i = 0; i < 2; i++)
#pragma unroll
            for (int h2 = 0; h2 < 2; h2++) {
                float mx = -1e30f;
#pragma unroll
                for (int j = 0; j < 8; j++)
                    mx = fmaxf(mx, fmaxf(c[i][j][h2*2], c[i][j][h2*2+1]));
                mx = fmaxf(mx, __shfl_xor_sync(0xffffffffu, mx, 1));
                mx = fmaxf(mx, __shfl_xor_sync(0xffffffffu, mx, 2));
                float s = 0.f;
#pragma unroll
                for (int j = 0; j < 8; j++) {
                    float e0 = __expf(c[i][j][h2*2]   - mx);
                    float e1 = __expf(c[i][j][h2*2+1] - mx);
                    c[i][j][h2*2] = e0; c[i][j][h2*2+1] = e1;
                    s += e0 + e1;
                }
                s += __shfl_xor_sync(0xffffffffu, s, 1);
                s += __shfl_xor_sync(0xffffffffu, s, 2);
                const float is = 1.0f / s;
                const size_t row = (size_t)(row0 + wr*32 + i*16 + h2*8 + g);
#pragma unroll
                for (int j = 0; j < 8; j++) {
                    __half2 h = __floats2half2_rn(c[i][j][h2*2]*is, c[i][j][h2*2+1]*is);
                    *(__half2*)(wOut + row * 512 + colbase + j*8 + t*2) = h;
                    float2 f = __half22float2(h);
                    cs[j*2] += f.x; cs[j*2+1] += f.y;
                }
            }

#pragma unroll
        for (int m = 0; m < 16; m++) {
            cs[m] += __shfl_xor_sync(0xffffffffu, cs[m], 4);
            cs[m] += __shfl_xor_sync(0xffffffffu, cs[m], 8);
            cs[m] += __shfl_xor_sync(0xffffffffu, cs[m], 16);
        }
        float* npsum = (float*)smem;
        if (lane < 4) {
#pragma unroll
            for (int j = 0; j < 8; j++) {
                npsum[wr*128 + wc*64 + j*8 + lane*2]     = cs[j*2];
                npsum[wr*128 + wc*64 + j*8 + lane*2 + 1] = cs[j*2+1];
            }
        }
        __syncthreads();
        if (tid < 128)
            npart[(size_t)blockIdx.y * 512 + col0 + tid] =
                npsum[tid] + npsum[128+tid] + npsum[256+tid] + npsum[384+tid];
    } else if (MODE == 1) {
        const int cg = col0 - 512 + wc * 64;
#pragma unroll
        for (int i = 0; i < 2; i++) {
            int rm = row0 + wr*32 + i*16 + g;
#pragma unroll
            for (int j = 0; j < 8; j++) {
                int cn = cg + j*8 + t*2;
                float b0 = biasB[cn], b1 = biasB[cn + 1];
                *(__half2*)(fxOut + (size_t)rm * 512 + cn) =
                    __floats2half2_rn(c[i][j][0] + b0, c[i][j][1] + b1);
                *(__half2*)(fxOut + (size_t)(rm + 8) * 512 + cn) =
                    __floats2half2_rn(c[i][j][2] + b0, c[i][j][3] + b1);
            }
        }
    } else {
        const int cg = col0 + wc * 64;
#pragma unroll
        for (int i = 0; i < 2; i++) {
            int rm = row0 + wr*32 + i*16 + g;
#pragma unroll
            for (int j = 0; j < 8; j++) {
                int cn = cg + j*8 + t*2;
                float b0 = biasA[cn], b1 = biasA[cn + 1];
                *(float2*)(outF + (size_t)rm * 512 + cn) =
                    make_float2(c[i][j][0] + b0, c[i][j][1] + b1);
                *(float2*)(outF + (size_t)(rm + 8) * 512 + cn) =
                    make_float2(c[i][j][2] + b0, c[i][j][3] + b1);
            }
        }
    }
}

// ============================================================
// tokens partials via tensor cores + norm stage 1 (block-range)
// ============================================================
#define WT 72
#define TPT_TILE_H (128 * WT)
#define TPT_SMEM (4 * TPT_TILE_H * 2)

__global__ __launch_bounds__(256) void tokpart_mma_kernel(
    const __half* __restrict__ fx, const __half* __restrict__ w,
    float* __restrict__ part,
    const float* __restrict__ npart, float* __restrict__ np2)
{
    extern __shared__ char smem[];
    const int tid  = threadIdx.x;

    if (blockIdx.x >= TOK_CHUNKS) {
        const int nb = (blockIdx.x - TOK_CHUNKS) * 16 + blockIdx.y;
        const int b = nb >> 4, rbg = nb & 15;
#pragma unroll
        for (int rep = 0; rep < 2; rep++) {
            const int hg = tid + rep * 256;
            float s = 0.f;
#pragma unroll
            for (int rb = 0; rb < 16; rb++)
                s += npart[((size_t)(b * 256 + rbg * 16 + rb)) * 512 + hg];
            np2[(size_t)nb * 512 + hg] = s;
        }
        return;
    }

    const int chunk = blockIdx.x;
    const int bh = blockIdx.y;
    const int b = bh >> 3, h = bh & 7;
    const size_t rbase = (size_t)b * NN + (size_t)chunk * 2048;

    const int lane = tid & 31;
    const int warp = tid >> 5;
    const int wm   = warp >> 1;
    const int wn   = warp & 1;

    const uint32_t S0 = (uint32_t)__cvta_generic_to_shared(smem);

    float c[4][4];
#pragma unroll
    for (int nj = 0; nj < 4; nj++)
#pragma unroll
        for (int r = 0; r < 4; r++) c[nj][r] = 0.f;

    const uint32_t aOff = (uint32_t)(((((lane >> 4) << 3) + (lane & 7)) * WT
                           + wm*16 + (((lane >> 3) & 1) << 3)) * 2);
    uint32_t bOff[2];
#pragma unroll
    for (int p2 = 0; p2 < 2; p2++)
        bOff[p2] = (uint32_t)((((((lane >> 3) & 1) << 3) + (lane & 7)) * WT
                    + wn*32 + p2*16 + ((lane >> 4) << 3)) * 2);

    auto stage = [&](int kt, int buf) {
        __half* wsb = (__half*)smem + buf * TPT_TILE_H;
        __half* fsb = (__half*)smem + 2 * TPT_TILE_H + buf * TPT_TILE_H;
#pragma unroll
        for (int it = 0; it < 4; it++) {
            int s = tid + it * 256;
            int r = s >> 3;
            int c8 = (s & 7) * 8;
            size_t row = rbase + (size_t)kt * 128 + r;
            cp16(&wsb[r * WT + c8], w  + row * 512 + h * 64 + c8);
            cp16(&fsb[r * WT + c8], fx + row * 512 + h * 64 + c8);
        }
    };

    stage(0, 0);
    asm volatile("cp.async.commit_group;");

    for (int kt = 0; kt < 16; kt++) {
        asm volatile("cp.async.wait_group 0;");
        __syncthreads();
        if (kt + 1 < 16) {
            stage(kt + 1, (kt + 1) & 1);
            asm volatile("cp.async.commit_group;");
        }
        const int buf = kt & 1;
        const uint32_t wBuf = S0 + buf * TPT_TILE_H * 2;
        const uint32_t fBuf = S0 + (2 + buf) * TPT_TILE_H * 2;
#pragma unroll
        for (int ks = 0; ks < 8; ks++) {
            const uint32_t ksB = (uint32_t)(ks * 16 * WT * 2);
            unsigned a[4], bb[4][2];
            LDSM4T(a[0], a[1], a[2], a[3], wBuf + aOff + ksB);
            LDSM4T(bb[0][0], bb[0][1], bb[1][0], bb[1][1], fBuf + bOff[0] + ksB);
            LDSM4T(bb[2][0], bb[2][1], bb[3][0], bb[3][1], fBuf + bOff[1] + ksB);
#pragma unroll
            for (int nj = 0; nj < 4; nj++)
                mma_f16(c[nj], a, bb[nj]);
        }
        __syncthreads();
    }

    const int g4 = lane >> 2;
    const int t  = lane & 3;
    float* p = part + ((size_t)bh * TOK_CHUNKS + chunk) * 4096;
#pragma unroll
    for (int nj = 0; nj < 4; nj++) {
        int col = wn*32 + nj*8 + t*2;
        *(float2*)&p[(wm*16 + g4) * 64 + col]     = make_float2(c[nj][0], c[nj][1]);
        *(float2*)&p[(wm*16 + g4 + 8) * 64 + col] = make_float2(c[nj][2], c[nj][3]);
    }
}

// ============================================================
// tiny attention — fuses tok/norm final reductions; ck/cv precomputed
// ============================================================
template<int NC>
__device__ __forceinline__ void row_gemm_cols(
    const float* __restrict__ xrow, int Kd,
    const float* __restrict__ W, const float* __restrict__ bias,
    float* __restrict__ outp, int c0)
{
    float acc[NC];
#pragma unroll
    for (int j = 0; j < NC; j++) acc[j] = bias[c0 + j];
    for (int d = 0; d < Kd; d++) {
        float xv = xrow[d];
        const float4* W4 = (const float4*)(W + (size_t)d * 64 + c0);
#pragma unroll
        for (int j4 = 0; j4 < NC/4; j4++) {
            float4 wv = W4[j4];
            acc[j4*4+0] += xv*wv.x; acc[j4*4+1] += xv*wv.y;
            acc[j4*4+2] += xv*wv.z; acc[j4*4+3] += xv*wv.w;
        }
    }
#pragma unroll
    for (int j = 0; j < NC; j++) outp[c0 + j] = acc[j];
}

__device__ __forceinline__ void attn_row(
    const float* __restrict__ qrow, const float* __restrict__ Kt,
    const float* __restrict__ Vt, float* __restrict__ o)
{
    float qr[64];
#pragma unroll
    for (int d = 0; d < 64; d++) qr[d] = qrow[d];
    float sc[64];
    float m = -1e30f;
    for (int j = 0; j < 64; j++) {
        const float4* kr = (const float4*)(Kt + j * 64);
        float a = 0.f;
#pragma unroll
        for (int d4 = 0; d4 < 16; d4++) {
            float4 kv = kr[d4];
            a += qr[d4*4]*kv.x + qr[d4*4+1]*kv.y + qr[d4*4+2]*kv.z + qr[d4*4+3]*kv.w;
        }
        sc[j] = a * 0.125f;
        m = fmaxf(m, sc[j]);
    }
    float s = 0.f;
#pragma unroll
    for (int j = 0; j < 64; j++) { sc[j] = __expf(sc[j] - m); s += sc[j]; }
    float is = 1.0f / s;
#pragma unroll
    for (int d = 0; d < 64; d++) o[d] = 0.f;
    for (int j = 0; j < 64; j++) {
        float p = sc[j] * is;
        const float4* vr = (const float4*)(Vt + j * 64);
#pragma unroll
        for (int d4 = 0; d4 < 16; d4++) {
            float4 vv = vr[d4];
            o[d4*4+0] += p*vv.x; o[d4*4+1] += p*vv.y;
            o[d4*4+2] += p*vv.z; o[d4*4+3] += p*vv.w;
        }
    }
}

__global__ __launch_bounds__(256) void attn_kernel(
    const float* __restrict__ ckv,
    const float* __restrict__ Wq, const float* __restrict__ bq,
    const float* __restrict__ Wk, const float* __restrict__ bk,
    const float* __restrict__ Wv, const float* __restrict__ bv,
    const float* __restrict__ Wcq, const float* __restrict__ bcq,
    const float* __restrict__ smix,
    const float* __restrict__ tpart, const float* __restrict__ np2,
    float* __restrict__ ot)
{
    extern __shared__ float sm[];
    float* s_tok  = sm;
    float* s_q    = sm + 4096;
    float* s_k    = sm + 2*4096;
    float* s_v    = sm + 3*4096;
    float* s_cq   = sm + 4*4096;
    float* s_ck   = sm + 5*4096;
    float* s_cv   = sm + 6*4096;
    float* s_norm = sm + 7*4096;

    const int bh = blockIdx.x;
    const int b = bh >> 3, h = bh & 7;
    const int tid = threadIdx.x;

    if (tid < 64) {
        float s = 0.f;
#pragma unroll
        for (int c = 0; c < 16; c++)
            s += np2[((size_t)(b * 16 + c)) * 512 + h * 64 + tid];
        s_norm[tid] = 1.0f / (s + EPS);
    }
    __syncthreads();

    for (int idx = tid; idx < 4096; idx += 256) {
        float s = 0.f;
#pragma unroll
        for (int c = 0; c < TOK_CHUNKS; c++)
            s += tpart[((size_t)bh * TOK_CHUNKS + c) * 4096 + idx];
        s_tok[idx] = s * s_norm[idx >> 6];
        s_ck[idx] = ckv[(size_t)bh * 4096 + idx];
        s_cv[idx] = ckv[(size_t)(16 + bh) * 4096 + idx];
    }
    __syncthreads();

    {
        const int pid = tid >> 6;
        const int i   = tid & 63;
        const float* W; const float* bb; float* dst;
        if (pid == 0)      { W = Wq;  bb = bq;  dst = s_q;  }
        else if (pid == 1) { W = Wk;  bb = bk;  dst = s_k;  }
        else if (pid == 2) { W = Wv;  bb = bv;  dst = s_v;  }
        else               { W = Wcq; bb = bcq; dst = s_cq; }
        row_gemm_cols<64>(&s_tok[i*64], 64, W, bb, &dst[i*64], 0);
    }
    __syncthreads();

    if (tid < 64) {
        float o[64];
        attn_row(&s_q[tid*64], s_k, s_v, o);
#pragma unroll
        for (int d = 0; d < 64; d++) s_tok[tid*64 + d] = o[d];
    } else if (tid < 128) {
        const int i = tid - 64;
        float o[64];
        attn_row(&s_cq[i*64], s_ck, s_cv, o);
#pragma unroll
        for (int d = 0; d < 64; d++) s_cq[i*64 + d] = o[d];
    }
    __syncthreads();

    const float gmix = 1.0f / (1.0f + __expf(-smix[0]));
    for (int idx = tid; idx < 4096; idx += 256)
        ot[(size_t)bh*4096 + idx] = gmix * s_tok[idx] + (1.0f - gmix) * s_cq[idx];
}

// ============================================================
// M^T[b][c][hg] = sum_d out_tok[b,hg,d] * Wo[h*64+d, c]  (fp16 out)
// ============================================================
__global__ __launch_bounds__(256) void m_kernel(
    const float* __restrict__ Wo, const float* __restrict__ ot,
    __half* __restrict__ MT)
{
    __shared__ float s_ot[4096];
    __shared__ float s_wo[64 * 128];
    const int bh = blockIdx.y;
    const int h = bh & 7, b = bh >> 3;
    const int c0 = blockIdx.x * 128;
    const int tid = threadIdx.x;

    for (int idx = tid; idx < 1024; idx += 256)
        ((float4*)s_ot)[idx] = ((const float4*)(ot + (size_t)bh * 4096))[idx];
    for (int idx = tid; idx < 2048; idx += 256) {
        int d = idx >> 5;
        int c4 = idx & 31;
        ((float4*)s_wo)[idx] = *(const float4*)(Wo + (size_t)(h*64 + d)*512 + c0 + c4*4);
    }
    __syncthreads();

    const int g0 = (tid >> 3) * 2;
    const int ct = (tid & 7) * 16;
    float acc[2][16];
#pragma unroll
    for (int g = 0; g < 2; g++)
#pragma unroll
        for (int c = 0; c < 16; c++) acc[g][c] = 0.f;

    for (int d = 0; d < 64; d++) {
        float a0 = s_ot[g0*64 + d];
        float a1 = s_ot[(g0+1)*64 + d];
#pragma unroll
        for (int c4 = 0; c4 < 4; c4++) {
            float4 wv = *(const float4*)&s_wo[d*128 + ct + c4*4];
            acc[0][c4*4+0]+=a0*wv.x; acc[0][c4*4+1]+=a0*wv.y; acc[0][c4*4+2]+=a0*wv.z; acc[0][c4*4+3]+=a0*wv.w;
            acc[1][c4*4+0]+=a1*wv.x; acc[1][c4*4+1]+=a1*wv.y; acc[1][c4*4+2]+=a1*wv.z; acc[1][c4*4+3]+=a1*wv.w;
        }
    }

#pragma unroll
    for (int g = 0; g < 2; g++) {
        int hg = h*64 + g0 + g;
#pragma unroll
        for (int c = 0; c < 16; c++)
            MT[(size_t)b * 262144 + (size_t)(c0 + ct + c) * 512 + hg] =
                __float2half_rn(acc[g][c]);
    }
}

// ============================================================
// host launcher
// ============================================================
extern "C" void kernel_launch(void* const* d_in, const int* in_sizes, int n_in,
                              void* d_out, int out_size)
{
    const float* x      = (const float*)d_in[0];
    const float* ctx    = (const float*)d_in[1];
    const float* Wx     = (const float*)d_in[2];
    const float* bx     = (const float*)d_in[3];
    const float* Wfx    = (const float*)d_in[4];
    const float* bfx    = (const float*)d_in[5];
    const float* Wslice = (const float*)d_in[6];
    const float* bslice = (const float*)d_in[7];
    const float* temp   = (const float*)d_in[8];
    const float* Wq     = (const float*)d_in[9];
    const float* bq     = (const float*)d_in[10];
    const float* Wk     = (const float*)d_in[11];
    const float* bk     = (const float*)d_in[12];
    const float* Wv     = (const float*)d_in[13];
    const float* bv     = (const float*)d_in[14];
    const float* Wcq    = (const float*)d_in[15];
    const float* bcq    = (const float*)d_in[16];
    const float* Wck    = (const float*)d_in[17];
    const float* bck    = (const float*)d_in[18];
    const float* Wcv    = (const float*)d_in[19];
    const float* bcv    = (const float*)d_in[20];
    const float* smix   = (const float*)d_in[21];
    const float* Wo     = (const float*)d_in[22];
    const float* bo     = (const float*)d_in[23];
    float* out = (float*)d_out;

    void *p;
    cudaGetSymbolAddress(&p, g_xh);    __half* xh    = (__half*)p;
    cudaGetSymbolAddress(&p, g_wh);    __half* wh    = (__half*)p;
    cudaGetSymbolAddress(&p, g_fxh);   __half* fxh   = (__half*)p;
    cudaGetSymbolAddress(&p, g_npart); float* npart  = (float*)p;
    cudaGetSymbolAddress(&p, g_np2);   float* np2    = (float*)p;
    cudaGetSymbolAddress(&p, g_tpart); float* tpart  = (float*)p;
    cudaGetSymbolAddress(&p, g_ot);    float* ot     = (float*)p;
    cudaGetSymbolAddress(&p, g_ckv);   float* ckv    = (float*)p;
    cudaGetSymbolAddress(&p, g_MTh);   __half* MTh   = (__half*)p;
    cudaGetSymbolAddress(&p, g_WcatTh);__half* WcatT = (__half*)p;
    cudaGetSymbolAddress(&p, g_bcomb); float* bcomb  = (float*)p;

    cudaFuncSetAttribute(f16_gemm<1>, cudaFuncAttributeMaxDynamicSharedMemorySize, SM_GEMM);
    cudaFuncSetAttribute(f16_gemm<0>, cudaFuncAttributeMaxDynamicSharedMemorySize, SM_GEMM);
    cudaFuncSetAttribute(tokpart_mma_kernel, cudaFuncAttributeMaxDynamicSharedMemorySize, TPT_SMEM);
    cudaFuncSetAttribute(attn_kernel, cudaFuncAttributeMaxDynamicSharedMemorySize, (7*4096+64)*4);

    // 0: fused prologue (x->fp16 | WcatT | bcomb | ck/cv)
    prep_kernel<<<PREP_BLKS, 256>>>(x, xh, Wfx, Wx, Wslice, temp, bx, bslice,
                                    WcatT, bcomb, ctx, Wck, bck, Wcv, bcv, ckv);
    // 1: merged fp16 GEMM: softmax->wh(+npart) | bias->fxh
    f16_gemm<1><<<dim3(8, 512), 256, SM_GEMM>>>(
        xh, WcatT, bcomb, bfx, wh, fxh, nullptr, npart, CC, 0, 0);
    // 2: tokens = w^T @ fx (tensor cores) + norm stage 1 (fused grid)
    tokpart_mma_kernel<<<dim3(TOK_CHUNKS + 2, 16), 256, TPT_SMEM>>>(
        fxh, wh, tpart, npart, np2);
    // 3: tiny attention (fuses tok/norm final reductions)
    attn_kernel<<<16, 256, (7*4096+64)*4>>>(ckv, Wq, bq, Wk, bk, Wv, bv,
                                            Wcq, bcq, smix, tpart, np2, ot);
    // 4: fold out_tok @ Wo -> M^T (fp16)
    m_kernel<<<dim3(4, 16), 256>>>(Wo, ot, MTh);
    // 5: out = w @ M[b] + bo (fp16 GEMM, B per-batch)
    f16_gemm<0><<<dim3(4, 512), 256, SM_GEMM>>>(
        wh, MTh, bo, nullptr, nullptr, nullptr, out, nullptr, INNER, NN, 512*512);
}